// round 9
// baseline (speedup 1.0000x reference)
#include <cuda_runtime.h>
#include <cuda_bf16.h>
#include <mma.h>
#include <math.h>

using namespace nvcuda;

// Problem shape (fixed): T=256, B=64, D=H=1024
#define TT 256
#define BB 64
#define HH 1024
#define NG 4096      // 4*H
#define TBm 16384    // T*B
#define PKCTA 128    // persistent CTAs (1 per SM, all co-resident)

// ---------------- scratch (device globals: allocation-free rule) -------------
__device__ float g_zx[(size_t)TBm * NG];       // x-projection (gemm out)
__device__ float g_zxp[(size_t)TBm * NG];      // repacked zx (+bias)
// h sequence, CTA-block-major: [t][cb(128)][row(64)][8] bf16, slot t = h(t)
__device__ __nv_bfloat16 g_hseqh[(size_t)(TT + 1) * BB * HH];
__device__ __nv_bfloat16 g_hseql[(size_t)(TT + 1) * BB * HH];
__device__ __nv_bfloat16 g_xh[(size_t)TBm * HH];    // x hi plane (row-major)
__device__ __nv_bfloat16 g_xl[(size_t)TBm * HH];    // x lo plane
__device__ __nv_bfloat16 g_wxh[(size_t)HH * NG];    // input-W hi
__device__ __nv_bfloat16 g_wxl[(size_t)HH * NG];    // input-W lo
__device__ __nv_bfloat16 g_wph[(size_t)HH * NG];    // packed recurrent W hi
__device__ __nv_bfloat16 g_wpl[(size_t)HH * NG];    // packed recurrent W lo
__device__ __align__(16) int g_bar[2 * TT];         // per-step flags

// ---------------- helpers ----------------------------------------------------
__device__ __forceinline__ void split_bf16(float x, __nv_bfloat16& hi, __nv_bfloat16& lo) {
    hi = __float2bfloat16(x);
    lo = __float2bfloat16(x - __bfloat162float(hi));
}
__device__ __forceinline__ float fsig(float x) {
    float e = __expf(-x);
    return __fdividef(1.0f, 1.0f + e);
}
__device__ __forceinline__ float ftanh(float x) {
    float e = __expf(2.0f * x);
    return 1.0f - __fdividef(2.0f, e + 1.0f);
}
__device__ __forceinline__ void cpa16(void* dst, const void* src) {
    unsigned d = (unsigned)__cvta_generic_to_shared(dst);
    asm volatile("cp.async.cg.shared.global [%0], [%1], 16;" :: "r"(d), "l"(src));
}
__device__ __forceinline__ int ldrelax(const int* p) {
    int v;
    asm volatile("ld.relaxed.gpu.global.b32 %0, [%1];" : "=r"(v) : "l"(p));
    return v;
}

__global__ void init_state_kernel(__nv_bfloat16* hh, __nv_bfloat16* hl, int* bar) {
    int i = blockIdx.x * blockDim.x + threadIdx.x;
    if (i < BB * HH) {                        // zero h(0) = slot 0 (layout-agnostic)
        hh[i] = __float2bfloat16(0.0f);
        hl[i] = __float2bfloat16(0.0f);
    }
    if (i < TT) bar[i] = 0;
}

// fp32 -> bf16 hi/lo planes (elementwise)
__global__ void split_plane_kernel(const float* __restrict__ a,
                                   __nv_bfloat16* __restrict__ hi,
                                   __nv_bfloat16* __restrict__ lo, size_t n) {
    for (size_t i = (size_t)blockIdx.x * blockDim.x + threadIdx.x; i < n;
         i += (size_t)gridDim.x * blockDim.x) {
        __nv_bfloat16 h, l;
        split_bf16(a[i], h, l);
        hi[i] = h;
        lo[i] = l;
    }
}

// input half of W (rows 0..1023) -> row-major bf16 planes [1024][4096]
__global__ void prep_wx_kernel(const float* __restrict__ W,
                               __nv_bfloat16* __restrict__ hi,
                               __nv_bfloat16* __restrict__ lo) {
    for (size_t o = (size_t)blockIdx.x * blockDim.x + threadIdx.x;
         o < (size_t)HH * NG; o += (size_t)gridDim.x * blockDim.x) {
        __nv_bfloat16 h, l;
        split_bf16(W[o], h, l);
        hi[o] = h;
        lo[o] = l;
    }
}

// recurrent half of W -> per-CTA contiguous slices:
// wp[(c*1024 + k)*32 + g*8 + j] = W[1024+k][g*1024 + c*8 + j]  (hi/lo planes)
__global__ void prep_w_kernel(const float* __restrict__ W,
                              __nv_bfloat16* __restrict__ hi,
                              __nv_bfloat16* __restrict__ lo) {
    for (size_t o = (size_t)blockIdx.x * blockDim.x + threadIdx.x;
         o < (size_t)HH * NG; o += (size_t)gridDim.x * blockDim.x) {
        int col = (int)(o & 31);
        int k   = (int)((o >> 5) & 1023);
        int c   = (int)(o >> 15);
        int g = col >> 3, j = col & 7;
        float v = W[(size_t)(HH + k) * NG + g * HH + c * 8 + j];
        __nv_bfloat16 vh, vl;
        split_bf16(v, vh, vl);
        hi[o] = vh;
        lo[o] = vl;
    }
}

// Repack zx (+bias) into per-(t, CTA) contiguous 8KB blocks
__global__ void repack_zx_kernel(const float* __restrict__ zx,
                                 const float* __restrict__ bias,
                                 float* __restrict__ zxp) {
    for (size_t o = (size_t)blockIdx.x * blockDim.x + threadIdx.x;
         o < (size_t)TBm * NG; o += (size_t)gridDim.x * blockDim.x) {
        int col = (int)(o & 31);
        int row = (int)((o >> 5) & 63);
        int c   = (int)((o >> 11) & 127);
        int t   = (int)(o >> 18);
        int g = col >> 3, j = col & 7;
        int n = g * HH + c * 8 + j;
        zxp[o] = zx[((size_t)t * BB + row) * NG + n] + bias[n];
    }
}

// ---------------- big input-projection GEMM (bf16 planes, 3-stage pipe) ------
// seq==0: A row-major [M][1024]. seq==1: A = hseq planes [t][cb][64][8], rows
// m map to (t = m>>6 + 1, row = m&63).
#define XBM 128
#define XBN 128
#define XBK 32
#define XST 3

struct GSmem {
    __nv_bfloat16 Ah[XST][XBM][XBK + 8];
    __nv_bfloat16 Al[XST][XBM][XBK + 8];
    __nv_bfloat16 Bh[XST][XBK][XBN + 8];
    __nv_bfloat16 Bl[XST][XBK][XBN + 8];
};

__global__ __launch_bounds__(256) void gemm_x_bf16(
    const __nv_bfloat16* __restrict__ Aph, const __nv_bfloat16* __restrict__ Apl,
    const __nv_bfloat16* __restrict__ Bph, const __nv_bfloat16* __restrict__ Bpl,
    float* __restrict__ Z, int seq)
{
    extern __shared__ unsigned char sraw[];
    GSmem* S = (GSmem*)sraw;

    const int bm = blockIdx.y * XBM;
    const int bn = blockIdx.x * XBN;
    const int tid = threadIdx.x;
    const int warp = tid >> 5;
    const int wm = (warp >> 2) * 64;
    const int wn = (warp & 3) * 32;

    auto load_stage = [&](int s, int kb) {
        if (seq == 0) {
#pragma unroll
            for (int p = 0; p < 2; ++p) {
                int i = tid + p * 256;
                int r = i >> 2, off = (i & 3) * 8;
                cpa16(&S->Ah[s][r][off], Aph + (size_t)(bm + r) * HH + kb + off);
                cpa16(&S->Al[s][r][off], Apl + (size_t)(bm + r) * HH + kb + off);
            }
        } else {
#pragma unroll
            for (int p = 0; p < 2; ++p) {
                int i = tid + p * 256;
                int r = i >> 2, cbl = i & 3;
                int t0 = (bm + r) >> 6, row = (bm + r) & 63;
                size_t src = (((size_t)(t0 + 1) * PKCTA + (kb >> 3) + cbl) * BB + row) * 8;
                cpa16(&S->Ah[s][r][cbl * 8], Aph + src);
                cpa16(&S->Al[s][r][cbl * 8], Apl + src);
            }
        }
#pragma unroll
        for (int p = 0; p < 2; ++p) {
            int i = tid + p * 256;
            int r = i >> 4, off = (i & 15) * 8;
            cpa16(&S->Bh[s][r][off], Bph + (size_t)(kb + r) * NG + bn + off);
            cpa16(&S->Bl[s][r][off], Bpl + (size_t)(kb + r) * NG + bn + off);
        }
    };

    load_stage(0, 0);
    asm volatile("cp.async.commit_group;" ::: "memory");
    load_stage(1, XBK);
    asm volatile("cp.async.commit_group;" ::: "memory");

    wmma::fragment<wmma::accumulator, 16, 16, 16, float> acc[4][2];
#pragma unroll
    for (int i = 0; i < 4; ++i)
#pragma unroll
        for (int j = 0; j < 2; ++j)
            wmma::fill_fragment(acc[i][j], 0.0f);

    const int NKT = HH / XBK;   // 32
    for (int kt = 0; kt < NKT; ++kt) {
        asm volatile("cp.async.wait_group 1;" ::: "memory");
        __syncthreads();
        int s = kt % XST;

#pragma unroll
        for (int kk = 0; kk < XBK; kk += 16) {
            wmma::fragment<wmma::matrix_a, 16, 16, 16, __nv_bfloat16, wmma::row_major> ah[4], al[4];
            wmma::fragment<wmma::matrix_b, 16, 16, 16, __nv_bfloat16, wmma::row_major> bh[2], bl[2];
#pragma unroll
            for (int i = 0; i < 4; ++i) {
                wmma::load_matrix_sync(ah[i], &S->Ah[s][wm + 16 * i][kk], XBK + 8);
                wmma::load_matrix_sync(al[i], &S->Al[s][wm + 16 * i][kk], XBK + 8);
            }
#pragma unroll
            for (int j = 0; j < 2; ++j) {
                wmma::load_matrix_sync(bh[j], &S->Bh[s][kk][wn + 16 * j], XBN + 8);
                wmma::load_matrix_sync(bl[j], &S->Bl[s][kk][wn + 16 * j], XBN + 8);
            }
#pragma unroll
            for (int i = 0; i < 4; ++i)
#pragma unroll
                for (int j = 0; j < 2; ++j) {
                    wmma::mma_sync(acc[i][j], ah[i], bh[j], acc[i][j]);
                    wmma::mma_sync(acc[i][j], ah[i], bl[j], acc[i][j]);
                    wmma::mma_sync(acc[i][j], al[i], bh[j], acc[i][j]);
                }
        }

        if (kt + 2 < NKT) load_stage((kt + 2) % XST, (kt + 2) * XBK);
        asm volatile("cp.async.commit_group;" ::: "memory");
    }

#pragma unroll
    for (int i = 0; i < 4; ++i)
#pragma unroll
        for (int j = 0; j < 2; ++j)
            wmma::store_matrix_sync(Z + (size_t)(bm + wm + 16 * i) * NG + bn + wn + 16 * j,
                                    acc[i][j], NG, wmma::mem_row_major);
}

// ---------------- persistent recurrent kernel ---------------------------------
// 128 CTAs x 256 threads. CTA c owns hidden cols [c*8, c*8+8). Warp (mt,kh)
// streams its own 16x32 h subtile through a private 3-slot cp.async ring; no
// intra-loop syncs. hseq is CTA-block-major so stores/loads are coalesced.
// Per-step inter-CTA sync: red.release counter + relaxed poll + ld.acquire.
#define CH 64        // k per chunk
#define NCH 16       // chunks per step
#define HSTW 40      // per-warp h tile stride (conflict-free ldsm)
#define WST 32       // W smem stride
#define ZST 36       // zs/zxs stride (conflict-free epilogue: bank = 4*row+jp)

struct PSmem {
    __nv_bfloat16 wh[HH][WST];          // 64 KB
    __nv_bfloat16 wl[HH][WST];          // 64 KB
    __nv_bfloat16 hws[8][3][16][HSTW];  // 30 KB
    __nv_bfloat16 lws[8][3][16][HSTW];  // 30 KB
    float zxs[BB][ZST];                 // 9 KB
    float zs[2][BB][ZST];               // 18 KB
    float cs[BB][12];                   // 3 KB
};                                      // 223,232 B

__global__ __launch_bounds__(256) void lstm_persist_kernel(
    const float* __restrict__ zxp,           // [256][128][64][32] packed (+bias)
    const __nv_bfloat16* __restrict__ wph,
    const __nv_bfloat16* __restrict__ wpl,
    __nv_bfloat16* __restrict__ hseqh,       // [257][128][64][8]
    __nv_bfloat16* __restrict__ hseql,
    float* __restrict__ hout_all,            // [256][64][1024] fp32 or null
    int* __restrict__ bar)                   // [TT]
{
    extern __shared__ unsigned char smem_raw[];
    PSmem* S = (PSmem*)smem_raw;

    const int tid  = threadIdx.x;
    const int warp = tid >> 5;
    const int lane = tid & 31;
    const int cblk = blockIdx.x;             // 0..127
    const int mt   = warp & 3;               // m-tile (16 rows)
    const int kh   = warp >> 2;              // k-half (0/1)
    const int wrow = mt * 16;

    // ---- load W slice into SMEM once ----
    for (int i = tid; i < HH * 4; i += 256) {
        int row = i >> 2, off = (i & 3) * 8;
        cpa16(&S->wh[row][off], wph + ((size_t)cblk * HH + row) * 32 + off);
        cpa16(&S->wl[row][off], wpl + ((size_t)cblk * HH + row) * 32 + off);
    }
    asm volatile("cp.async.commit_group;\ncp.async.wait_group 0;" ::: "memory");
    for (int e = tid; e < BB * 12; e += 256) ((float*)S->cs)[e] = 0.0f;
    __syncthreads();

    // fusion thread mapping (fixed): row = tid>>2, jp = tid&3; cols jp, jp+4
    const int frow = tid >> 2;
    const int fjp  = tid & 3;

    for (int t = 0; t < TT; ++t) {
        const __nv_bfloat16* hin_h = hseqh + (size_t)t * BB * HH;
        const __nv_bfloat16* hin_l = hseql + (size_t)t * BB * HH;
        __nv_bfloat16* hout_h = hseqh + (size_t)(t + 1) * BB * HH + (size_t)cblk * (BB * 8);
        __nv_bfloat16* hout_l = hseql + (size_t)(t + 1) * BB * HH + (size_t)cblk * (BB * 8);

        // ---- issue zx loads BEFORE the poll (independent of h(t)) ----
        {
            const float* zsrc = zxp + ((size_t)t * PKCTA + cblk) * (BB * 32);
#pragma unroll
            for (int p = 0; p < 2; ++p) {
                int i = tid + p * 256;           // 512 x 16B chunks
                int r = i >> 3, seg = i & 7;
                cpa16((char*)&S->zxs[r][0] + seg * 16, zsrc + r * 32 + seg * 4);
            }
        }

        // ---- wait until h(t) fully published ----
        if (t > 0) {
            const int* f = bar + t - 1;
            if (lane == 0) {
                while (ldrelax(f) < PKCTA) __nanosleep(32);
            }
            __syncwarp();
            int v;
            asm volatile("ld.acquire.gpu.global.b32 %0, [%1];" : "=r"(v) : "l"(f) : "memory");
        }

        // per-warp private chunk loader: 16 rows x 32 k (4 source cbs)
        auto wload = [&](int slot, int ic) {
            int cbbase = ic * 8 + kh * 4;
#pragma unroll
            for (int p = 0; p < 2; ++p) {
                int cbl = lane >> 3, rlo = (lane & 7) + p * 8;
                size_t src = (((size_t)(cbbase + cbl)) * BB + wrow + rlo) * 8;
                cpa16(&S->hws[warp][slot][rlo][cbl * 8], hin_h + src);
                cpa16(&S->lws[warp][slot][rlo][cbl * 8], hin_l + src);
            }
        };

        wload(0, 0);
        asm volatile("cp.async.commit_group;" ::: "memory");   // zx rides with chunk0
        wload(1, 1);
        asm volatile("cp.async.commit_group;" ::: "memory");
        wload(2, 2);
        asm volatile("cp.async.commit_group;" ::: "memory");

        wmma::fragment<wmma::accumulator, 16, 16, 16, float> acc[2][3];
#pragma unroll
        for (int nt = 0; nt < 2; ++nt)
#pragma unroll
            for (int p = 0; p < 3; ++p)
                wmma::fill_fragment(acc[nt][p], 0.0f);

        // ---- sync-free per-warp chunk loop ----
        for (int ic = 0; ic < NCH; ++ic) {
            asm volatile("cp.async.wait_group 2;" ::: "memory");
            int sl = ic % 3;

#pragma unroll
            for (int kk = 0; kk < 2; ++kk) {
                wmma::fragment<wmma::matrix_a, 16, 16, 16, __nv_bfloat16, wmma::row_major> ah, al;
                wmma::load_matrix_sync(ah, &S->hws[warp][sl][0][kk * 16], HSTW);
                wmma::load_matrix_sync(al, &S->lws[warp][sl][0][kk * 16], HSTW);
                int krow = ic * CH + kh * 32 + kk * 16;
#pragma unroll
                for (int nt = 0; nt < 2; ++nt) {
                    wmma::fragment<wmma::matrix_b, 16, 16, 16, __nv_bfloat16, wmma::row_major> bh, bl;
                    wmma::load_matrix_sync(bh, &S->wh[krow][nt * 16], WST);
                    wmma::load_matrix_sync(bl, &S->wl[krow][nt * 16], WST);
                    wmma::mma_sync(acc[nt][0], ah, bh, acc[nt][0]);
                    wmma::mma_sync(acc[nt][1], ah, bl, acc[nt][1]);
                    wmma::mma_sync(acc[nt][2], al, bh, acc[nt][2]);
                }
            }

            if (ic + 3 < NCH) wload((ic + 3) % 3, ic + 3);
            asm volatile("cp.async.commit_group;" ::: "memory");
        }
        asm volatile("cp.async.wait_group 0;" ::: "memory");

        // ---- sum 3 passes, park partials (ldm=36, conflict-free reads later) ----
#pragma unroll
        for (int nt = 0; nt < 2; ++nt) {
#pragma unroll
            for (int e = 0; e < acc[nt][0].num_elements; ++e)
                acc[nt][0].x[e] += acc[nt][1].x[e] + acc[nt][2].x[e];
            wmma::store_matrix_sync(&S->zs[kh][mt * 16][nt * 16], acc[nt][0], ZST,
                                    wmma::mem_row_major);
        }
        __syncthreads();

        // ---- gate fusion: thread (frow, fjp) handles cols fjp and fjp+4 ----
        {
            float nh2[2];
#pragma unroll
            for (int q = 0; q < 2; ++q) {
                int j = fjp + q * 4;
                float zi = S->zs[0][frow][j]      + S->zs[1][frow][j]      + S->zxs[frow][j];
                float zj = S->zs[0][frow][8 + j]  + S->zs[1][frow][8 + j]  + S->zxs[frow][8 + j];
                float zf = S->zs[0][frow][16 + j] + S->zs[1][frow][16 + j] + S->zxs[frow][16 + j];
                float zo = S->zs[0][frow][24 + j] + S->zs[1][frow][24 + j] + S->zxs[frow][24 + j];
                float cold = S->cs[frow][j];
                float nc = cold * fsig(zf + 1.0f) + fsig(zi) * ftanh(zj);
                float nh = ftanh(nc) * fsig(zo);
                S->cs[frow][j] = nc;
                nh2[q] = nh;
                __nv_bfloat16 hi, lo;
                split_bf16(nh, hi, lo);
                // coalesced: CTA block is contiguous [64][8]
                hout_h[frow * 8 + j] = hi;
                hout_l[frow * 8 + j] = lo;
            }
            __syncthreads();
            // ---- publish flag (release) ----
            if (tid == 0)
                asm volatile("red.release.gpu.global.add.u32 [%0], 1;"
                             :: "l"(bar + t) : "memory");
            // fp32 output (off critical path, after release)
            if (hout_all) {
                size_t ob = (size_t)t * BB * HH + (size_t)frow * HH + cblk * 8;
                hout_all[ob + fjp] = nh2[0];
                hout_all[ob + fjp + 4] = nh2[1];
            }
        }
    }
}

// ---------------- launch ------------------------------------------------------
extern "C" void kernel_launch(void* const* d_in, const int* in_sizes, int n_in,
                              void* d_out, int out_size)
{
    const float* x  = (const float*)d_in[0];
    const float* W0 = (const float*)d_in[1];
    const float* b0 = (const float*)d_in[2];
    const float* W1 = (const float*)d_in[3];
    const float* b1 = (const float*)d_in[4];
    float* out = (float*)d_out;

    float *zx, *zxp;
    __nv_bfloat16 *hseqh, *hseql, *xh, *xl, *wxh, *wxl, *wph, *wpl;
    int* bar;
    cudaGetSymbolAddress((void**)&zx,    g_zx);
    cudaGetSymbolAddress((void**)&zxp,   g_zxp);
    cudaGetSymbolAddress((void**)&hseqh, g_hseqh);
    cudaGetSymbolAddress((void**)&hseql, g_hseql);
    cudaGetSymbolAddress((void**)&xh,    g_xh);
    cudaGetSymbolAddress((void**)&xl,    g_xl);
    cudaGetSymbolAddress((void**)&wxh,   g_wxh);
    cudaGetSymbolAddress((void**)&wxl,   g_wxl);
    cudaGetSymbolAddress((void**)&wph,   g_wph);
    cudaGetSymbolAddress((void**)&wpl,   g_wpl);
    cudaGetSymbolAddress((void**)&bar,   g_bar);

    const int psmem = (int)sizeof(PSmem);
    cudaFuncSetAttribute(lstm_persist_kernel,
                         cudaFuncAttributeMaxDynamicSharedMemorySize, psmem);
    const int gsmem = (int)sizeof(GSmem);
    cudaFuncSetAttribute(gemm_x_bf16,
                         cudaFuncAttributeMaxDynamicSharedMemorySize, gsmem);

    const dim3 ggrid(NG / XBN, TBm / XBM);   // (32, 128)

    // ---- layer 0 ----
    split_plane_kernel<<<2048, 256>>>(x, xh, xl, (size_t)TBm * HH);
    prep_wx_kernel<<<2048, 256>>>(W0, wxh, wxl);
    prep_w_kernel<<<2048, 256>>>(W0, wph, wpl);
    init_state_kernel<<<(BB * HH + 255) / 256, 256>>>(hseqh, hseql, bar);
    gemm_x_bf16<<<ggrid, 256, gsmem>>>(xh, xl, wxh, wxl, zx, 0);
    repack_zx_kernel<<<8192, 256>>>(zx, b0, zxp);
    lstm_persist_kernel<<<PKCTA, 256, psmem>>>(zxp, wph, wpl, hseqh, hseql,
                                               (float*)0, bar);

    // ---- layer 1 (gemm A = h sequence planes, slots 1..256) ----
    prep_wx_kernel<<<2048, 256>>>(W1, wxh, wxl);
    prep_w_kernel<<<2048, 256>>>(W1, wph, wpl);
    init_state_kernel<<<(BB * HH + 255) / 256, 256>>>(hseqh, hseql, bar + TT);
    gemm_x_bf16<<<ggrid, 256, gsmem>>>(hseqh, hseql, wxh, wxl, zx, 1);
    repack_zx_kernel<<<8192, 256>>>(zx, b1, zxp);
    lstm_persist_kernel<<<PKCTA, 256, psmem>>>(zxp, wph, wpl, hseqh, hseql,
                                               out, bar + TT);
}

// round 12
// speedup vs baseline: 1.0093x; 1.0093x over previous
#include <cuda_runtime.h>
#include <cuda_bf16.h>
#include <mma.h>
#include <math.h>

using namespace nvcuda;

// Problem shape (fixed): T=256, B=64, D=H=1024
#define TT 256
#define BB 64
#define HH 1024
#define NG 4096      // 4*H
#define TBm 16384    // T*B
#define PKCTA 128    // persistent CTAs (1 per SM, all co-resident)

// ---------------- scratch (device globals: allocation-free rule) -------------
__device__ float g_zx[(size_t)TBm * NG];       // x-projection (gemm out)
__device__ float g_zxp[(size_t)TBm * NG];      // repacked zx (+bias)
// h sequence, CTA-block-major: [t][cb(128)][row(64)][8] bf16, slot t = h(t)
__device__ __nv_bfloat16 g_hseqh[(size_t)(TT + 1) * BB * HH];
__device__ __nv_bfloat16 g_hseql[(size_t)(TT + 1) * BB * HH];
__device__ __nv_bfloat16 g_xh[(size_t)TBm * HH];    // x hi plane (row-major)
__device__ __nv_bfloat16 g_xl[(size_t)TBm * HH];    // x lo plane
__device__ __nv_bfloat16 g_wxh[(size_t)HH * NG];    // input-W hi
__device__ __nv_bfloat16 g_wxl[(size_t)HH * NG];    // input-W lo
__device__ __nv_bfloat16 g_wph[(size_t)HH * NG];    // packed recurrent W hi
__device__ __nv_bfloat16 g_wpl[(size_t)HH * NG];    // packed recurrent W lo
__device__ __align__(16) int g_bar[2 * TT];         // per-step flags

// ---------------- helpers ----------------------------------------------------
__device__ __forceinline__ void split_bf16(float x, __nv_bfloat16& hi, __nv_bfloat16& lo) {
    hi = __float2bfloat16(x);
    lo = __float2bfloat16(x - __bfloat162float(hi));
}
__device__ __forceinline__ float fsig(float x) {
    float e = __expf(-x);
    return __fdividef(1.0f, 1.0f + e);
}
__device__ __forceinline__ float ftanh(float x) {
    float e = __expf(2.0f * x);
    return 1.0f - __fdividef(2.0f, e + 1.0f);
}
__device__ __forceinline__ void cpa16(void* dst, const void* src) {
    unsigned d = (unsigned)__cvta_generic_to_shared(dst);
    asm volatile("cp.async.cg.shared.global [%0], [%1], 16;" :: "r"(d), "l"(src));
}
__device__ __forceinline__ int ldrelax(const int* p) {
    int v;
    asm volatile("ld.relaxed.gpu.global.b32 %0, [%1];" : "=r"(v) : "l"(p));
    return v;
}

__global__ void init_state_kernel(__nv_bfloat16* hh, __nv_bfloat16* hl, int* bar) {
    int i = blockIdx.x * blockDim.x + threadIdx.x;
    if (i < BB * HH) {                        // zero h(0) = slot 0 (layout-agnostic)
        hh[i] = __float2bfloat16(0.0f);
        hl[i] = __float2bfloat16(0.0f);
    }
    if (i < TT) bar[i] = 0;
}

// fp32 -> bf16 hi/lo planes (elementwise)
__global__ void split_plane_kernel(const float* __restrict__ a,
                                   __nv_bfloat16* __restrict__ hi,
                                   __nv_bfloat16* __restrict__ lo, size_t n) {
    for (size_t i = (size_t)blockIdx.x * blockDim.x + threadIdx.x; i < n;
         i += (size_t)gridDim.x * blockDim.x) {
        __nv_bfloat16 h, l;
        split_bf16(a[i], h, l);
        hi[i] = h;
        lo[i] = l;
    }
}

// input half of W (rows 0..1023) -> row-major bf16 planes [1024][4096]
__global__ void prep_wx_kernel(const float* __restrict__ W,
                               __nv_bfloat16* __restrict__ hi,
                               __nv_bfloat16* __restrict__ lo) {
    for (size_t o = (size_t)blockIdx.x * blockDim.x + threadIdx.x;
         o < (size_t)HH * NG; o += (size_t)gridDim.x * blockDim.x) {
        __nv_bfloat16 h, l;
        split_bf16(W[o], h, l);
        hi[o] = h;
        lo[o] = l;
    }
}

// recurrent half of W -> per-CTA contiguous slices:
// wp[(c*1024 + k)*32 + g*8 + j] = W[1024+k][g*1024 + c*8 + j]  (hi/lo planes)
__global__ void prep_w_kernel(const float* __restrict__ W,
                              __nv_bfloat16* __restrict__ hi,
                              __nv_bfloat16* __restrict__ lo) {
    for (size_t o = (size_t)blockIdx.x * blockDim.x + threadIdx.x;
         o < (size_t)HH * NG; o += (size_t)gridDim.x * blockDim.x) {
        int col = (int)(o & 31);
        int k   = (int)((o >> 5) & 1023);
        int c   = (int)(o >> 15);
        int g = col >> 3, j = col & 7;
        float v = W[(size_t)(HH + k) * NG + g * HH + c * 8 + j];
        __nv_bfloat16 vh, vl;
        split_bf16(v, vh, vl);
        hi[o] = vh;
        lo[o] = vl;
    }
}

// Repack zx (+bias) into per-(t, CTA) contiguous 8KB blocks
__global__ void repack_zx_kernel(const float* __restrict__ zx,
                                 const float* __restrict__ bias,
                                 float* __restrict__ zxp) {
    for (size_t o = (size_t)blockIdx.x * blockDim.x + threadIdx.x;
         o < (size_t)TBm * NG; o += (size_t)gridDim.x * blockDim.x) {
        int col = (int)(o & 31);
        int row = (int)((o >> 5) & 63);
        int c   = (int)((o >> 11) & 127);
        int t   = (int)(o >> 18);
        int g = col >> 3, j = col & 7;
        int n = g * HH + c * 8 + j;
        zxp[o] = zx[((size_t)t * BB + row) * NG + n] + bias[n];
    }
}

// ---------------- big input-projection GEMM (bf16 planes, 3-stage pipe) ------
// seq==0: A row-major [M][1024]. seq==1: A = hseq planes [t][cb][64][8], rows
// m map to (t = m>>6 + 1, row = m&63).
#define XBM 128
#define XBN 128
#define XBK 32
#define XST 3

struct GSmem {
    __nv_bfloat16 Ah[XST][XBM][XBK + 8];
    __nv_bfloat16 Al[XST][XBM][XBK + 8];
    __nv_bfloat16 Bh[XST][XBK][XBN + 8];
    __nv_bfloat16 Bl[XST][XBK][XBN + 8];
};

__global__ __launch_bounds__(256) void gemm_x_bf16(
    const __nv_bfloat16* __restrict__ Aph, const __nv_bfloat16* __restrict__ Apl,
    const __nv_bfloat16* __restrict__ Bph, const __nv_bfloat16* __restrict__ Bpl,
    float* __restrict__ Z, int seq)
{
    extern __shared__ unsigned char sraw[];
    GSmem* S = (GSmem*)sraw;

    const int bm = blockIdx.y * XBM;
    const int bn = blockIdx.x * XBN;
    const int tid = threadIdx.x;
    const int warp = tid >> 5;
    const int wm = (warp >> 2) * 64;
    const int wn = (warp & 3) * 32;

    auto load_stage = [&](int s, int kb) {
        if (seq == 0) {
#pragma unroll
            for (int p = 0; p < 2; ++p) {
                int i = tid + p * 256;
                int r = i >> 2, off = (i & 3) * 8;
                cpa16(&S->Ah[s][r][off], Aph + (size_t)(bm + r) * HH + kb + off);
                cpa16(&S->Al[s][r][off], Apl + (size_t)(bm + r) * HH + kb + off);
            }
        } else {
#pragma unroll
            for (int p = 0; p < 2; ++p) {
                int i = tid + p * 256;
                int r = i >> 2, cbl = i & 3;
                int t0 = (bm + r) >> 6, row = (bm + r) & 63;
                size_t src = (((size_t)(t0 + 1) * PKCTA + (kb >> 3) + cbl) * BB + row) * 8;
                cpa16(&S->Ah[s][r][cbl * 8], Aph + src);
                cpa16(&S->Al[s][r][cbl * 8], Apl + src);
            }
        }
#pragma unroll
        for (int p = 0; p < 2; ++p) {
            int i = tid + p * 256;
            int r = i >> 4, off = (i & 15) * 8;
            cpa16(&S->Bh[s][r][off], Bph + (size_t)(kb + r) * NG + bn + off);
            cpa16(&S->Bl[s][r][off], Bpl + (size_t)(kb + r) * NG + bn + off);
        }
    };

    load_stage(0, 0);
    asm volatile("cp.async.commit_group;" ::: "memory");
    load_stage(1, XBK);
    asm volatile("cp.async.commit_group;" ::: "memory");

    wmma::fragment<wmma::accumulator, 16, 16, 16, float> acc[4][2];
#pragma unroll
    for (int i = 0; i < 4; ++i)
#pragma unroll
        for (int j = 0; j < 2; ++j)
            wmma::fill_fragment(acc[i][j], 0.0f);

    const int NKT = HH / XBK;   // 32
    for (int kt = 0; kt < NKT; ++kt) {
        asm volatile("cp.async.wait_group 1;" ::: "memory");
        __syncthreads();
        int s = kt % XST;

#pragma unroll
        for (int kk = 0; kk < XBK; kk += 16) {
            wmma::fragment<wmma::matrix_a, 16, 16, 16, __nv_bfloat16, wmma::row_major> ah[4], al[4];
            wmma::fragment<wmma::matrix_b, 16, 16, 16, __nv_bfloat16, wmma::row_major> bh[2], bl[2];
#pragma unroll
            for (int i = 0; i < 4; ++i) {
                wmma::load_matrix_sync(ah[i], &S->Ah[s][wm + 16 * i][kk], XBK + 8);
                wmma::load_matrix_sync(al[i], &S->Al[s][wm + 16 * i][kk], XBK + 8);
            }
#pragma unroll
            for (int j = 0; j < 2; ++j) {
                wmma::load_matrix_sync(bh[j], &S->Bh[s][kk][wn + 16 * j], XBN + 8);
                wmma::load_matrix_sync(bl[j], &S->Bl[s][kk][wn + 16 * j], XBN + 8);
            }
#pragma unroll
            for (int i = 0; i < 4; ++i)
#pragma unroll
                for (int j = 0; j < 2; ++j) {
                    wmma::mma_sync(acc[i][j], ah[i], bh[j], acc[i][j]);
                    wmma::mma_sync(acc[i][j], ah[i], bl[j], acc[i][j]);
                    wmma::mma_sync(acc[i][j], al[i], bh[j], acc[i][j]);
                }
        }

        if (kt + 2 < NKT) load_stage((kt + 2) % XST, (kt + 2) * XBK);
        asm volatile("cp.async.commit_group;" ::: "memory");
    }

#pragma unroll
    for (int i = 0; i < 4; ++i)
#pragma unroll
        for (int j = 0; j < 2; ++j)
            wmma::store_matrix_sync(Z + (size_t)(bm + wm + 16 * i) * NG + bn + wn + 16 * j,
                                    acc[i][j], NG, wmma::mem_row_major);
}

// ---------------- persistent recurrent kernel ---------------------------------
// 128 CTAs x 256 threads. CTA c owns hidden cols [c*8, c*8+8). Warp (mt,kh)
// streams its own 16x32 h subtile through a private 3-slot cp.async ring; no
// intra-loop syncs. hseq is CTA-block-major so stores/loads are coalesced.
// Per-step inter-CTA sync: red.release counter + relaxed poll + ld.acquire.
#define CH 64        // k per chunk
#define NCH 16       // chunks per step
#define HSTW 40      // per-warp h tile stride (conflict-free ldsm)
#define WST 32       // W smem stride
#define ZST 36       // zs/zxs stride (conflict-free epilogue: bank = 4*row+jp)

struct PSmem {
    __nv_bfloat16 wh[HH][WST];          // 64 KB
    __nv_bfloat16 wl[HH][WST];          // 64 KB
    __nv_bfloat16 hws[8][3][16][HSTW];  // 30 KB
    __nv_bfloat16 lws[8][3][16][HSTW];  // 30 KB
    float zxs[BB][ZST];                 // 9 KB
    float zs[2][BB][ZST];               // 18 KB
    float cs[BB][12];                   // 3 KB
};                                      // 223,232 B

__global__ __launch_bounds__(256) void lstm_persist_kernel(
    const float* __restrict__ zxp,           // [256][128][64][32] packed (+bias)
    const __nv_bfloat16* __restrict__ wph,
    const __nv_bfloat16* __restrict__ wpl,
    __nv_bfloat16* __restrict__ hseqh,       // [257][128][64][8]
    __nv_bfloat16* __restrict__ hseql,
    float* __restrict__ hout_all,            // [256][64][1024] fp32 or null
    int* __restrict__ bar)                   // [TT]
{
    extern __shared__ unsigned char smem_raw[];
    PSmem* S = (PSmem*)smem_raw;

    const int tid  = threadIdx.x;
    const int warp = tid >> 5;
    const int lane = tid & 31;
    const int cblk = blockIdx.x;             // 0..127
    const int mt   = warp & 3;               // m-tile (16 rows)
    const int kh   = warp >> 2;              // k-half (0/1)
    const int wrow = mt * 16;

    // ---- load W slice into SMEM once ----
    for (int i = tid; i < HH * 4; i += 256) {
        int row = i >> 2, off = (i & 3) * 8;
        cpa16(&S->wh[row][off], wph + ((size_t)cblk * HH + row) * 32 + off);
        cpa16(&S->wl[row][off], wpl + ((size_t)cblk * HH + row) * 32 + off);
    }
    asm volatile("cp.async.commit_group;\ncp.async.wait_group 0;" ::: "memory");
    for (int e = tid; e < BB * 12; e += 256) ((float*)S->cs)[e] = 0.0f;
    __syncthreads();

    // fusion thread mapping (fixed): row = tid>>2, jp = tid&3; cols jp, jp+4
    const int frow = tid >> 2;
    const int fjp  = tid & 3;

    for (int t = 0; t < TT; ++t) {
        const __nv_bfloat16* hin_h = hseqh + (size_t)t * BB * HH;
        const __nv_bfloat16* hin_l = hseql + (size_t)t * BB * HH;
        __nv_bfloat16* hout_h = hseqh + (size_t)(t + 1) * BB * HH + (size_t)cblk * (BB * 8);
        __nv_bfloat16* hout_l = hseql + (size_t)(t + 1) * BB * HH + (size_t)cblk * (BB * 8);

        // ---- issue zx loads BEFORE the poll (independent of h(t)) ----
        {
            const float* zsrc = zxp + ((size_t)t * PKCTA + cblk) * (BB * 32);
#pragma unroll
            for (int p = 0; p < 2; ++p) {
                int i = tid + p * 256;           // 512 x 16B chunks
                int r = i >> 3, seg = i & 7;
                cpa16((char*)&S->zxs[r][0] + seg * 16, zsrc + r * 32 + seg * 4);
            }
        }

        // ---- wait until h(t) fully published ----
        if (t > 0) {
            const int* f = bar + t - 1;
            if (lane == 0) {
                while (ldrelax(f) < PKCTA) __nanosleep(32);
            }
            __syncwarp();
            int v;
            asm volatile("ld.acquire.gpu.global.b32 %0, [%1];" : "=r"(v) : "l"(f) : "memory");
        }

        // per-warp private chunk loader: 16 rows x 32 k (4 source cbs)
        auto wload = [&](int slot, int ic) {
            int cbbase = ic * 8 + kh * 4;
#pragma unroll
            for (int p = 0; p < 2; ++p) {
                int cbl = lane >> 3, rlo = (lane & 7) + p * 8;
                size_t src = (((size_t)(cbbase + cbl)) * BB + wrow + rlo) * 8;
                cpa16(&S->hws[warp][slot][rlo][cbl * 8], hin_h + src);
                cpa16(&S->lws[warp][slot][rlo][cbl * 8], hin_l + src);
            }
        };

        wload(0, 0);
        asm volatile("cp.async.commit_group;" ::: "memory");   // zx rides with chunk0
        wload(1, 1);
        asm volatile("cp.async.commit_group;" ::: "memory");
        wload(2, 2);
        asm volatile("cp.async.commit_group;" ::: "memory");

        wmma::fragment<wmma::accumulator, 16, 16, 16, float> acc[2][3];
#pragma unroll
        for (int nt = 0; nt < 2; ++nt)
#pragma unroll
            for (int p = 0; p < 3; ++p)
                wmma::fill_fragment(acc[nt][p], 0.0f);

        // ---- sync-free per-warp chunk loop ----
        for (int ic = 0; ic < NCH; ++ic) {
            asm volatile("cp.async.wait_group 2;" ::: "memory");
            int sl = ic % 3;

#pragma unroll
            for (int kk = 0; kk < 2; ++kk) {
                wmma::fragment<wmma::matrix_a, 16, 16, 16, __nv_bfloat16, wmma::row_major> ah, al;
                wmma::load_matrix_sync(ah, &S->hws[warp][sl][0][kk * 16], HSTW);
                wmma::load_matrix_sync(al, &S->lws[warp][sl][0][kk * 16], HSTW);
                int krow = ic * CH + kh * 32 + kk * 16;
#pragma unroll
                for (int nt = 0; nt < 2; ++nt) {
                    wmma::fragment<wmma::matrix_b, 16, 16, 16, __nv_bfloat16, wmma::row_major> bh, bl;
                    wmma::load_matrix_sync(bh, &S->wh[krow][nt * 16], WST);
                    wmma::load_matrix_sync(bl, &S->wl[krow][nt * 16], WST);
                    wmma::mma_sync(acc[nt][0], ah, bh, acc[nt][0]);
                    wmma::mma_sync(acc[nt][1], ah, bl, acc[nt][1]);
                    wmma::mma_sync(acc[nt][2], al, bh, acc[nt][2]);
                }
            }

            if (ic + 3 < NCH) wload((ic + 3) % 3, ic + 3);
            asm volatile("cp.async.commit_group;" ::: "memory");
        }
        asm volatile("cp.async.wait_group 0;" ::: "memory");

        // ---- sum 3 passes, park partials (ldm=36, conflict-free reads later) ----
#pragma unroll
        for (int nt = 0; nt < 2; ++nt) {
#pragma unroll
            for (int e = 0; e < acc[nt][0].num_elements; ++e)
                acc[nt][0].x[e] += acc[nt][1].x[e] + acc[nt][2].x[e];
            wmma::store_matrix_sync(&S->zs[kh][mt * 16][nt * 16], acc[nt][0], ZST,
                                    wmma::mem_row_major);
        }
        __syncthreads();

        // ---- gate fusion: thread (frow, fjp) handles cols fjp and fjp+4 ----
        {
            float nh2[2];
#pragma unroll
            for (int q = 0; q < 2; ++q) {
                int j = fjp + q * 4;
                float zi = S->zs[0][frow][j]      + S->zs[1][frow][j]      + S->zxs[frow][j];
                float zj = S->zs[0][frow][8 + j]  + S->zs[1][frow][8 + j]  + S->zxs[frow][8 + j];
                float zf = S->zs[0][frow][16 + j] + S->zs[1][frow][16 + j] + S->zxs[frow][16 + j];
                float zo = S->zs[0][frow][24 + j] + S->zs[1][frow][24 + j] + S->zxs[frow][24 + j];
                float cold = S->cs[frow][j];
                float nc = cold * fsig(zf + 1.0f) + fsig(zi) * ftanh(zj);
                float nh = ftanh(nc) * fsig(zo);
                S->cs[frow][j] = nc;
                nh2[q] = nh;
                __nv_bfloat16 hi, lo;
                split_bf16(nh, hi, lo);
                // coalesced: CTA block is contiguous [64][8]
                hout_h[frow * 8 + j] = hi;
                hout_l[frow * 8 + j] = lo;
            }
            __syncthreads();
            // ---- publish flag (release) ----
            if (tid == 0)
                asm volatile("red.release.gpu.global.add.u32 [%0], 1;"
                             :: "l"(bar + t) : "memory");
            // fp32 output (off critical path, after release)
            if (hout_all) {
                size_t ob = (size_t)t * BB * HH + (size_t)frow * HH + cblk * 8;
                hout_all[ob + fjp] = nh2[0];
                hout_all[ob + fjp + 4] = nh2[1];
            }
        }
    }
}

// ---------------- launch ------------------------------------------------------
extern "C" void kernel_launch(void* const* d_in, const int* in_sizes, int n_in,
                              void* d_out, int out_size)
{
    const float* x  = (const float*)d_in[0];
    const float* W0 = (const float*)d_in[1];
    const float* b0 = (const float*)d_in[2];
    const float* W1 = (const float*)d_in[3];
    const float* b1 = (const float*)d_in[4];
    float* out = (float*)d_out;

    float *zx, *zxp;
    __nv_bfloat16 *hseqh, *hseql, *xh, *xl, *wxh, *wxl, *wph, *wpl;
    int* bar;
    cudaGetSymbolAddress((void**)&zx,    g_zx);
    cudaGetSymbolAddress((void**)&zxp,   g_zxp);
    cudaGetSymbolAddress((void**)&hseqh, g_hseqh);
    cudaGetSymbolAddress((void**)&hseql, g_hseql);
    cudaGetSymbolAddress((void**)&xh,    g_xh);
    cudaGetSymbolAddress((void**)&xl,    g_xl);
    cudaGetSymbolAddress((void**)&wxh,   g_wxh);
    cudaGetSymbolAddress((void**)&wxl,   g_wxl);
    cudaGetSymbolAddress((void**)&wph,   g_wph);
    cudaGetSymbolAddress((void**)&wpl,   g_wpl);
    cudaGetSymbolAddress((void**)&bar,   g_bar);

    const int psmem = (int)sizeof(PSmem);
    cudaFuncSetAttribute(lstm_persist_kernel,
                         cudaFuncAttributeMaxDynamicSharedMemorySize, psmem);
    const int gsmem = (int)sizeof(GSmem);
    cudaFuncSetAttribute(gemm_x_bf16,
                         cudaFuncAttributeMaxDynamicSharedMemorySize, gsmem);

    const dim3 ggrid(NG / XBN, TBm / XBM);   // (32, 128)

    // ---- layer 0 ----
    split_plane_kernel<<<2048, 256>>>(x, xh, xl, (size_t)TBm * HH);
    prep_wx_kernel<<<2048, 256>>>(W0, wxh, wxl);
    prep_w_kernel<<<2048, 256>>>(W0, wph, wpl);
    init_state_kernel<<<(BB * HH + 255) / 256, 256>>>(hseqh, hseql, bar);
    gemm_x_bf16<<<ggrid, 256, gsmem>>>(xh, xl, wxh, wxl, zx, 0);
    repack_zx_kernel<<<8192, 256>>>(zx, b0, zxp);
    lstm_persist_kernel<<<PKCTA, 256, psmem>>>(zxp, wph, wpl, hseqh, hseql,
                                               (float*)0, bar);

    // ---- layer 1 (gemm A = h sequence planes, slots 1..256) ----
    prep_wx_kernel<<<2048, 256>>>(W1, wxh, wxl);
    prep_w_kernel<<<2048, 256>>>(W1, wph, wpl);
    init_state_kernel<<<(BB * HH + 255) / 256, 256>>>(hseqh, hseql, bar + TT);
    gemm_x_bf16<<<ggrid, 256, gsmem>>>(hseqh, hseql, wxh, wxl, zx, 1);
    repack_zx_kernel<<<8192, 256>>>(zx, b1, zxp);
    lstm_persist_kernel<<<PKCTA, 256, psmem>>>(zxp, wph, wpl, hseqh, hseql,
                                               out, bar + TT);
}

// round 14
// speedup vs baseline: 1.6112x; 1.5963x over previous
#include <cuda_runtime.h>
#include <cuda_bf16.h>
#include <cuda_fp16.h>
#include <mma.h>
#include <math.h>

using namespace nvcuda;

// Problem shape (fixed): T=256, B=64, D=H=1024
#define TT 256
#define BB 64
#define HH 1024
#define NG 4096      // 4*H
#define TBm 16384    // T*B
#define PKCTA 128    // persistent CTAs

// ---------------- scratch (device globals) ------------------------------------
__device__ float g_zx[(size_t)TBm * NG];
__device__ float g_zxp[(size_t)TBm * NG];
// h sequence, CTA-block-major: [slot(257)][cb(128)][row(64)][8] fp16
__device__ __align__(128) __half g_hseq[(size_t)(TT + 1) * BB * HH];
__device__ __align__(128) __half g_xf[(size_t)TBm * HH];     // x fp16 (row-major)
__device__ __align__(128) __half g_wxh[(size_t)HH * NG];     // input-W fp16 hi
__device__ __align__(128) __half g_wxl[(size_t)HH * NG];     // input-W fp16 lo
__device__ __align__(128) __half g_wph[(size_t)HH * NG];     // packed recurrent W hi
__device__ __align__(128) __half g_wpl[(size_t)HH * NG];     // packed recurrent W lo
__device__ __align__(16) int g_bar[2 * TT];

// ---------------- helpers ------------------------------------------------------
__device__ __forceinline__ void split_f16(float x, __half& hi, __half& lo) {
    hi = __float2half(x);
    lo = __float2half(x - __half2float(hi));
}
__device__ __forceinline__ float fsig(float x) { return __fdividef(1.0f, 1.0f + __expf(-x)); }
__device__ __forceinline__ float ftanh(float x) { return 1.0f - __fdividef(2.0f, __expf(2.0f * x) + 1.0f); }
__device__ __forceinline__ void cpa16(void* dst, const void* src) {
    unsigned d = (unsigned)__cvta_generic_to_shared(dst);
    asm volatile("cp.async.cg.shared.global [%0], [%1], 16;" :: "r"(d), "l"(src));
}
__device__ __forceinline__ int ldrelax(const int* p) {
    int v; asm volatile("ld.relaxed.gpu.global.b32 %0, [%1];" : "=r"(v) : "l"(p)); return v;
}

__global__ void init_state_kernel(__half* hseq, int* bar) {
    int i = blockIdx.x * blockDim.x + threadIdx.x;
    if (i < BB * HH) hseq[i] = __float2half(0.0f);   // slot 0 = h(0) = 0
    if (i < TT) bar[i] = 0;
}

// fp32 -> single fp16 plane
__global__ void tof16_kernel(const float* __restrict__ a, __half* __restrict__ o, size_t n) {
    for (size_t i = (size_t)blockIdx.x * blockDim.x + threadIdx.x; i < n;
         i += (size_t)gridDim.x * blockDim.x)
        o[i] = __float2half(a[i]);
}

// input half of W (rows 0..1023) -> fp16 hi/lo planes [1024][4096]
__global__ void prep_wx_kernel(const float* __restrict__ W,
                               __half* __restrict__ hi, __half* __restrict__ lo) {
    for (size_t o = (size_t)blockIdx.x * blockDim.x + threadIdx.x;
         o < (size_t)HH * NG; o += (size_t)gridDim.x * blockDim.x) {
        __half h, l; split_f16(W[o], h, l); hi[o] = h; lo[o] = l;
    }
}

// recurrent half of W -> per-CTA contiguous slices (fp16 hi/lo):
// wp[(c*1024 + k)*32 + g*8 + j] = W[1024+k][g*1024 + c*8 + j]
__global__ void prep_w_kernel(const float* __restrict__ W,
                              __half* __restrict__ hi, __half* __restrict__ lo) {
    for (size_t o = (size_t)blockIdx.x * blockDim.x + threadIdx.x;
         o < (size_t)HH * NG; o += (size_t)gridDim.x * blockDim.x) {
        int col = (int)(o & 31);
        int k   = (int)((o >> 5) & 1023);
        int c   = (int)(o >> 15);
        int g = col >> 3, j = col & 7;
        float v = W[(size_t)(HH + k) * NG + g * HH + c * 8 + j];
        __half vh, vl; split_f16(v, vh, vl);
        hi[o] = vh; lo[o] = vl;
    }
}

// Repack zx (+bias) into per-(t, CTA) contiguous 8KB blocks
__global__ void repack_zx_kernel(const float* __restrict__ zx,
                                 const float* __restrict__ bias,
                                 float* __restrict__ zxp) {
    for (size_t o = (size_t)blockIdx.x * blockDim.x + threadIdx.x;
         o < (size_t)TBm * NG; o += (size_t)gridDim.x * blockDim.x) {
        int col = (int)(o & 31);
        int row = (int)((o >> 5) & 63);
        int c   = (int)((o >> 11) & 127);
        int t   = (int)(o >> 18);
        int n = (col >> 3) * HH + c * 8 + (col & 7);
        zxp[o] = zx[((size_t)t * BB + row) * NG + n] + bias[n];
    }
}

// ---------------- big input-projection GEMM (fp16 2-pass, 3-stage pipe) -------
// seq==0: A = xf row-major [M][1024]. seq==1: A = hseq [t0+1][cb][64][8].
#define XBM 128
#define XBN 128
#define XBK 32
#define XST 3

struct GSmem {
    __half Af[XST][XBM][XBK + 8];
    __half Bh[XST][XBK][XBN + 8];
    __half Bl[XST][XBK][XBN + 8];
};

__global__ __launch_bounds__(256) void gemm_x_f16(
    const __half* __restrict__ Af, const __half* __restrict__ hseq,
    const __half* __restrict__ Bph, const __half* __restrict__ Bpl,
    float* __restrict__ Z, int seq)
{
    extern __shared__ unsigned char sraw[];
    GSmem* S = (GSmem*)sraw;

    const int bm = blockIdx.y * XBM;
    const int bn = blockIdx.x * XBN;
    const int tid = threadIdx.x;
    const int warp = tid >> 5;
    const int wm = (warp >> 2) * 64;
    const int wn = (warp & 3) * 32;

    auto load_stage = [&](int s, int kb) {
        // A: 128 x 32 fp16 = 512 x 16B chunks (2 per thread)
#pragma unroll
        for (int p = 0; p < 2; ++p) {
            int i = tid + p * 256;
            int r = i >> 2, cbl = i & 3;
            if (seq == 0) {
                cpa16(&S->Af[s][r][cbl * 8], Af + (size_t)(bm + r) * HH + kb + cbl * 8);
            } else {
                int m = bm + r, t0 = m >> 6, row = m & 63;
                size_t src = (((size_t)(t0 + 1) * PKCTA + (kb >> 3) + cbl) * BB + row) * 8;
                cpa16(&S->Af[s][r][cbl * 8], hseq + src);
            }
        }
        // B hi/lo: 32 x 128 fp16 each = 512 x 16B chunks each
#pragma unroll
        for (int p = 0; p < 2; ++p) {
            int i = tid + p * 256;
            int r = i >> 4, off = (i & 15) * 8;
            cpa16(&S->Bh[s][r][off], Bph + (size_t)(kb + r) * NG + bn + off);
            cpa16(&S->Bl[s][r][off], Bpl + (size_t)(kb + r) * NG + bn + off);
        }
    };

    load_stage(0, 0);
    asm volatile("cp.async.commit_group;" ::: "memory");
    load_stage(1, XBK);
    asm volatile("cp.async.commit_group;" ::: "memory");

    wmma::fragment<wmma::accumulator, 16, 16, 16, float> acc[4][2];
#pragma unroll
    for (int i = 0; i < 4; ++i)
#pragma unroll
        for (int j = 0; j < 2; ++j) wmma::fill_fragment(acc[i][j], 0.0f);

    const int NKT = HH / XBK;   // 32
    for (int kt = 0; kt < NKT; ++kt) {
        asm volatile("cp.async.wait_group 1;" ::: "memory");
        __syncthreads();
        int s = kt % XST;

#pragma unroll
        for (int kk = 0; kk < XBK; kk += 16) {
            wmma::fragment<wmma::matrix_a, 16, 16, 16, __half, wmma::row_major> af[4];
            wmma::fragment<wmma::matrix_b, 16, 16, 16, __half, wmma::row_major> bh[2], bl[2];
#pragma unroll
            for (int i = 0; i < 4; ++i)
                wmma::load_matrix_sync(af[i], &S->Af[s][wm + 16 * i][kk], XBK + 8);
#pragma unroll
            for (int j = 0; j < 2; ++j) {
                wmma::load_matrix_sync(bh[j], &S->Bh[s][kk][wn + 16 * j], XBN + 8);
                wmma::load_matrix_sync(bl[j], &S->Bl[s][kk][wn + 16 * j], XBN + 8);
            }
#pragma unroll
            for (int i = 0; i < 4; ++i)
#pragma unroll
                for (int j = 0; j < 2; ++j) {
                    wmma::mma_sync(acc[i][j], af[i], bh[j], acc[i][j]);
                    wmma::mma_sync(acc[i][j], af[i], bl[j], acc[i][j]);
                }
        }

        if (kt + 2 < NKT) load_stage((kt + 2) % XST, (kt + 2) * XBK);
        asm volatile("cp.async.commit_group;" ::: "memory");
    }

#pragma unroll
    for (int i = 0; i < 4; ++i)
#pragma unroll
        for (int j = 0; j < 2; ++j)
            wmma::store_matrix_sync(Z + (size_t)(bm + wm + 16 * i) * NG + bn + wn + 16 * j,
                                    acc[i][j], NG, wmma::mem_row_major);
}

// ---------------- persistent recurrent kernel (fp16 2-pass) -------------------
// 128 CTAs x 256 threads. CTA c owns hidden cols [c*8, c*8+8). Warp (mt,kh)
// streams its own 16x32 fp16 h subtile through a private 3-slot cp.async ring;
// no intra-loop syncs. 2 passes: acc0 += a*Whi, acc1 += a*Wlo.
#define CH 64
#define NCH 16
#define HSTW 40
#define WST 32
#define ZST 36

struct PSmem {
    __half wh[HH][WST];               // 64 KB
    __half wl[HH][WST];               // 64 KB
    __half hws[8][3][16][HSTW];       // 15 KB
    float zxs[BB][ZST];               // 9 KB
    float zs[2][BB][ZST];             // 18 KB
    float cs[BB][12];                 // 3 KB
};                                    // ~173 KB

__global__ __launch_bounds__(256) void lstm_persist_kernel(
    const float* __restrict__ zxp,           // [256][128][64][32] (+bias)
    const __half* __restrict__ wph,
    const __half* __restrict__ wpl,
    __half* __restrict__ hseq,               // [257][128][64][8]
    float* __restrict__ hout_all,            // fp32 out or null
    int* __restrict__ bar)
{
    extern __shared__ unsigned char smem_raw[];
    PSmem* S = (PSmem*)smem_raw;

    const int tid  = threadIdx.x;
    const int warp = tid >> 5;
    const int lane = tid & 31;
    const int cblk = blockIdx.x;
    const int mt   = warp & 3;
    const int kh   = warp >> 2;
    const int wrow = mt * 16;

    // W hi/lo resident in SMEM
    for (int i = tid; i < HH * 4; i += 256) {
        int row = i >> 2, off = (i & 3) * 8;
        cpa16(&S->wh[row][off], wph + ((size_t)cblk * HH + row) * 32 + off);
        cpa16(&S->wl[row][off], wpl + ((size_t)cblk * HH + row) * 32 + off);
    }
    asm volatile("cp.async.commit_group;\ncp.async.wait_group 0;" ::: "memory");
    for (int e = tid; e < BB * 12; e += 256) ((float*)S->cs)[e] = 0.0f;
    __syncthreads();

    const int frow = tid >> 2;
    const int fjp  = tid & 3;

    for (int t = 0; t < TT; ++t) {
        const __half* hin = hseq + (size_t)t * BB * HH;
        __half* hout = hseq + (size_t)(t + 1) * BB * HH + (size_t)cblk * (BB * 8);

        // zx loads issued before the poll (independent of h(t))
        {
            const float* zsrc = zxp + ((size_t)t * PKCTA + cblk) * (BB * 32);
#pragma unroll
            for (int p = 0; p < 2; ++p) {
                int i = tid + p * 256;
                int r = i >> 3, seg = i & 7;
                cpa16((char*)&S->zxs[r][0] + seg * 16, zsrc + r * 32 + seg * 4);
            }
        }

        if (t > 0) {
            const int* f = bar + t - 1;
            if (lane == 0) {
                while (ldrelax(f) < PKCTA) __nanosleep(32);
            }
            __syncwarp();
            int v;
            asm volatile("ld.acquire.gpu.global.b32 %0, [%1];" : "=r"(v) : "l"(f) : "memory");
        }

        auto wload = [&](int slot, int ic) {
            int cbbase = ic * 8 + kh * 4;
            int cbl = lane >> 3;
#pragma unroll
            for (int p = 0; p < 2; ++p) {
                int rlo = (lane & 7) + p * 8;
                size_t src = (((size_t)(cbbase + cbl)) * BB + wrow + rlo) * 8;
                cpa16(&S->hws[warp][slot][rlo][cbl * 8], hin + src);
            }
        };

        wload(0, 0);
        asm volatile("cp.async.commit_group;" ::: "memory");
        wload(1, 1);
        asm volatile("cp.async.commit_group;" ::: "memory");
        wload(2, 2);
        asm volatile("cp.async.commit_group;" ::: "memory");

        wmma::fragment<wmma::accumulator, 16, 16, 16, float> acc[2][2];
#pragma unroll
        for (int nt = 0; nt < 2; ++nt)
#pragma unroll
            for (int p = 0; p < 2; ++p) wmma::fill_fragment(acc[nt][p], 0.0f);

        for (int ic = 0; ic < NCH; ++ic) {
            asm volatile("cp.async.wait_group 2;" ::: "memory");
            int sl = ic % 3;

#pragma unroll
            for (int kk = 0; kk < 2; ++kk) {
                wmma::fragment<wmma::matrix_a, 16, 16, 16, __half, wmma::row_major> af;
                wmma::load_matrix_sync(af, &S->hws[warp][sl][0][kk * 16], HSTW);
                int krow = ic * CH + kh * 32 + kk * 16;
#pragma unroll
                for (int nt = 0; nt < 2; ++nt) {
                    wmma::fragment<wmma::matrix_b, 16, 16, 16, __half, wmma::row_major> bh, bl;
                    wmma::load_matrix_sync(bh, &S->wh[krow][nt * 16], WST);
                    wmma::load_matrix_sync(bl, &S->wl[krow][nt * 16], WST);
                    wmma::mma_sync(acc[nt][0], af, bh, acc[nt][0]);
                    wmma::mma_sync(acc[nt][1], af, bl, acc[nt][1]);
                }
            }

            if (ic + 3 < NCH) wload((ic + 3) % 3, ic + 3);
            asm volatile("cp.async.commit_group;" ::: "memory");
        }
        asm volatile("cp.async.wait_group 0;" ::: "memory");

#pragma unroll
        for (int nt = 0; nt < 2; ++nt) {
#pragma unroll
            for (int e = 0; e < acc[nt][0].num_elements; ++e)
                acc[nt][0].x[e] += acc[nt][1].x[e];
            wmma::store_matrix_sync(&S->zs[kh][mt * 16][nt * 16], acc[nt][0], ZST,
                                    wmma::mem_row_major);
        }
        __syncthreads();

        // gate fusion: thread (frow, fjp) handles cols fjp and fjp+4
        {
            float nh2[2];
#pragma unroll
            for (int q = 0; q < 2; ++q) {
                int j = fjp + q * 4;
                float zi = S->zs[0][frow][j]      + S->zs[1][frow][j]      + S->zxs[frow][j];
                float zj = S->zs[0][frow][8 + j]  + S->zs[1][frow][8 + j]  + S->zxs[frow][8 + j];
                float zf = S->zs[0][frow][16 + j] + S->zs[1][frow][16 + j] + S->zxs[frow][16 + j];
                float zo = S->zs[0][frow][24 + j] + S->zs[1][frow][24 + j] + S->zxs[frow][24 + j];
                float cold = S->cs[frow][j];
                float nc = cold * fsig(zf + 1.0f) + fsig(zi) * ftanh(zj);
                float nh = ftanh(nc) * fsig(zo);
                S->cs[frow][j] = nc;
                nh2[q] = nh;
                hout[frow * 8 + j] = __float2half(nh);
            }
            __syncthreads();
            if (tid == 0)
                asm volatile("red.release.gpu.global.add.u32 [%0], 1;"
                             :: "l"(bar + t) : "memory");
            if (hout_all) {
                size_t ob = (size_t)t * BB * HH + (size_t)frow * HH + cblk * 8;
                hout_all[ob + fjp] = nh2[0];
                hout_all[ob + fjp + 4] = nh2[1];
            }
        }
    }
}

// ---------------- launch ------------------------------------------------------
extern "C" void kernel_launch(void* const* d_in, const int* in_sizes, int n_in,
                              void* d_out, int out_size)
{
    const float* x  = (const float*)d_in[0];
    const float* W0 = (const float*)d_in[1];
    const float* b0 = (const float*)d_in[2];
    const float* W1 = (const float*)d_in[3];
    const float* b1 = (const float*)d_in[4];
    float* out = (float*)d_out;

    float *zx, *zxp;
    __half *hseq, *xf, *wxh, *wxl, *wph, *wpl;
    int* bar;
    cudaGetSymbolAddress((void**)&zx,   g_zx);
    cudaGetSymbolAddress((void**)&zxp,  g_zxp);
    cudaGetSymbolAddress((void**)&hseq, g_hseq);
    cudaGetSymbolAddress((void**)&xf,   g_xf);
    cudaGetSymbolAddress((void**)&wxh,  g_wxh);
    cudaGetSymbolAddress((void**)&wxl,  g_wxl);
    cudaGetSymbolAddress((void**)&wph,  g_wph);
    cudaGetSymbolAddress((void**)&wpl,  g_wpl);
    cudaGetSymbolAddress((void**)&bar,  g_bar);

    const int psmem = (int)sizeof(PSmem);
    cudaFuncSetAttribute(lstm_persist_kernel,
                         cudaFuncAttributeMaxDynamicSharedMemorySize, psmem);
    const int gsmem = (int)sizeof(GSmem);
    cudaFuncSetAttribute(gemm_x_f16,
                         cudaFuncAttributeMaxDynamicSharedMemorySize, gsmem);

    const dim3 ggrid(NG / XBN, TBm / XBM);   // (32, 128)

    // ---- layer 0 ----
    tof16_kernel<<<2048, 256>>>(x, xf, (size_t)TBm * HH);
    prep_wx_kernel<<<2048, 256>>>(W0, wxh, wxl);
    prep_w_kernel<<<2048, 256>>>(W0, wph, wpl);
    init_state_kernel<<<(BB * HH + 255) / 256, 256>>>(hseq, bar);
    gemm_x_f16<<<ggrid, 256, gsmem>>>(xf, hseq, wxh, wxl, zx, 0);
    repack_zx_kernel<<<8192, 256>>>(zx, b0, zxp);
    lstm_persist_kernel<<<PKCTA, 256, psmem>>>(zxp, wph, wpl, hseq, (float*)0, bar);

    // ---- layer 1 (gemm A = h sequence, slots 1..256) ----
    prep_wx_kernel<<<2048, 256>>>(W1, wxh, wxl);
    prep_w_kernel<<<2048, 256>>>(W1, wph, wpl);
    gemm_x_f16<<<ggrid, 256, gsmem>>>(xf, hseq, wxh, wxl, zx, 1);
    init_state_kernel<<<(BB * HH + 255) / 256, 256>>>(hseq, bar + TT);
    repack_zx_kernel<<<8192, 256>>>(zx, b1, zxp);
    lstm_persist_kernel<<<PKCTA, 256, psmem>>>(zxp, wph, wpl, hseq, out, bar + TT);
}

// round 15
// speedup vs baseline: 1.6669x; 1.0346x over previous
#include <cuda_runtime.h>
#include <cuda_bf16.h>
#include <cuda_fp16.h>
#include <mma.h>
#include <math.h>

using namespace nvcuda;

// Problem shape (fixed): T=256, B=64, D=H=1024
#define TT 256
#define BB 64
#define HH 1024
#define NG 4096      // 4*H
#define TBm 16384    // T*B
#define PKCTA 128    // persistent CTAs

// ---------------- scratch (device globals) ------------------------------------
__device__ float g_zxp[(size_t)TBm * NG];      // packed x-projection (+bias)
// h sequence, CTA-block-major: [slot(257)][cb(128)][row(64)][8] fp16
__device__ __align__(128) __half g_hseq[(size_t)(TT + 1) * BB * HH];
__device__ __align__(128) __half g_xf[(size_t)TBm * HH];     // x fp16 (row-major)
__device__ __align__(128) __half g_wxh[(size_t)HH * NG];     // input-W fp16 hi
__device__ __align__(128) __half g_wxl[(size_t)HH * NG];     // input-W fp16 lo
__device__ __align__(128) __half g_wph[(size_t)HH * NG];     // packed recurrent W hi
__device__ __align__(128) __half g_wpl[(size_t)HH * NG];     // packed recurrent W lo
__device__ __align__(16) int g_bar[2 * TT];

// ---------------- helpers ------------------------------------------------------
__device__ __forceinline__ void split_f16(float x, __half& hi, __half& lo) {
    hi = __float2half(x);
    lo = __float2half(x - __half2float(hi));
}
__device__ __forceinline__ float fsig(float x) { return __fdividef(1.0f, 1.0f + __expf(-x)); }
__device__ __forceinline__ float ftanh(float x) { return 1.0f - __fdividef(2.0f, __expf(2.0f * x) + 1.0f); }
__device__ __forceinline__ void cpa16(void* dst, const void* src) {
    unsigned d = (unsigned)__cvta_generic_to_shared(dst);
    asm volatile("cp.async.cg.shared.global [%0], [%1], 16;" :: "r"(d), "l"(src));
}
__device__ __forceinline__ int ldrelax(const int* p) {
    int v; asm volatile("ld.relaxed.gpu.global.b32 %0, [%1];" : "=r"(v) : "l"(p)); return v;
}

__global__ void init_state_kernel(__half* hseq, int* bar) {
    int i = blockIdx.x * blockDim.x + threadIdx.x;
    if (i < BB * HH) hseq[i] = __float2half(0.0f);   // slot 0 = h(0) = 0
    if (i < TT) bar[i] = 0;
}

// fp32 -> single fp16 plane
__global__ void tof16_kernel(const float* __restrict__ a, __half* __restrict__ o, size_t n) {
    for (size_t i = (size_t)blockIdx.x * blockDim.x + threadIdx.x; i < n;
         i += (size_t)gridDim.x * blockDim.x)
        o[i] = __float2half(a[i]);
}

// input half of W (rows 0..1023) -> fp16 hi/lo planes [1024][4096]
__global__ void prep_wx_kernel(const float* __restrict__ W,
                               __half* __restrict__ hi, __half* __restrict__ lo) {
    for (size_t o = (size_t)blockIdx.x * blockDim.x + threadIdx.x;
         o < (size_t)HH * NG; o += (size_t)gridDim.x * blockDim.x) {
        __half h, l; split_f16(W[o], h, l); hi[o] = h; lo[o] = l;
    }
}

// recurrent half of W -> per-CTA contiguous slices (fp16 hi/lo)
__global__ void prep_w_kernel(const float* __restrict__ W,
                              __half* __restrict__ hi, __half* __restrict__ lo) {
    for (size_t o = (size_t)blockIdx.x * blockDim.x + threadIdx.x;
         o < (size_t)HH * NG; o += (size_t)gridDim.x * blockDim.x) {
        int col = (int)(o & 31);
        int k   = (int)((o >> 5) & 1023);
        int c   = (int)(o >> 15);
        int g = col >> 3, j = col & 7;
        float v = W[(size_t)(HH + k) * NG + g * HH + c * 8 + j];
        __half vh, vl; split_f16(v, vh, vl);
        hi[o] = vh; hi[o] = vh; lo[o] = vl;
    }
}

// ---------------- big input-projection GEMM (fp16, fused bias+repack) ---------
// seq==0: A = xf row-major. seq==1: A = hseq [t0+1][cb][64][8].
// Output written DIRECTLY in zxp packed layout (+bias): no repack kernel.
#define XBM 128
#define XBN 128
#define XBK 32
#define XST 3

struct GSmem {
    union {
        struct {
            __half Af[XST][XBM][XBK + 8];
            __half Bh[XST][XBK][XBN + 8];
            __half Bl[XST][XBK][XBN + 8];
        } p;
        float stage[XBM][XBN + 8];      // epilogue staging (69.6 KB <= 81 KB)
    };
};

template <int NPASS>
__global__ __launch_bounds__(256) void gemm_x_f16(
    const __half* __restrict__ Af, const __half* __restrict__ hseq,
    const __half* __restrict__ Bph, const __half* __restrict__ Bpl,
    const float* __restrict__ bias, float* __restrict__ zxp, int seq)
{
    extern __shared__ unsigned char sraw[];
    GSmem* S = (GSmem*)sraw;

    const int bm = blockIdx.y * XBM;
    const int bn = blockIdx.x * XBN;
    const int tid = threadIdx.x;
    const int warp = tid >> 5;
    const int wm = (warp >> 2) * 64;
    const int wn = (warp & 3) * 32;

    auto load_stage = [&](int s, int kb) {
#pragma unroll
        for (int p = 0; p < 2; ++p) {
            int i = tid + p * 256;
            int r = i >> 2, cbl = i & 3;
            if (seq == 0) {
                cpa16(&S->p.Af[s][r][cbl * 8], Af + (size_t)(bm + r) * HH + kb + cbl * 8);
            } else {
                int m = bm + r, t0 = m >> 6, row = m & 63;
                size_t src = (((size_t)(t0 + 1) * PKCTA + (kb >> 3) + cbl) * BB + row) * 8;
                cpa16(&S->p.Af[s][r][cbl * 8], hseq + src);
            }
        }
#pragma unroll
        for (int p = 0; p < 2; ++p) {
            int i = tid + p * 256;
            int r = i >> 4, off = (i & 15) * 8;
            cpa16(&S->p.Bh[s][r][off], Bph + (size_t)(kb + r) * NG + bn + off);
            if (NPASS == 2)
                cpa16(&S->p.Bl[s][r][off], Bpl + (size_t)(kb + r) * NG + bn + off);
        }
    };

    load_stage(0, 0);
    asm volatile("cp.async.commit_group;" ::: "memory");
    load_stage(1, XBK);
    asm volatile("cp.async.commit_group;" ::: "memory");

    wmma::fragment<wmma::accumulator, 16, 16, 16, float> acc[4][2];
#pragma unroll
    for (int i = 0; i < 4; ++i)
#pragma unroll
        for (int j = 0; j < 2; ++j) wmma::fill_fragment(acc[i][j], 0.0f);

    const int NKT = HH / XBK;   // 32
    for (int kt = 0; kt < NKT; ++kt) {
        asm volatile("cp.async.wait_group 1;" ::: "memory");
        __syncthreads();
        int s = kt % XST;

#pragma unroll
        for (int kk = 0; kk < XBK; kk += 16) {
            wmma::fragment<wmma::matrix_a, 16, 16, 16, __half, wmma::row_major> af[4];
            wmma::fragment<wmma::matrix_b, 16, 16, 16, __half, wmma::row_major> bh[2], bl[2];
#pragma unroll
            for (int i = 0; i < 4; ++i)
                wmma::load_matrix_sync(af[i], &S->p.Af[s][wm + 16 * i][kk], XBK + 8);
#pragma unroll
            for (int j = 0; j < 2; ++j) {
                wmma::load_matrix_sync(bh[j], &S->p.Bh[s][kk][wn + 16 * j], XBN + 8);
                if (NPASS == 2)
                    wmma::load_matrix_sync(bl[j], &S->p.Bl[s][kk][wn + 16 * j], XBN + 8);
            }
#pragma unroll
            for (int i = 0; i < 4; ++i)
#pragma unroll
                for (int j = 0; j < 2; ++j) {
                    wmma::mma_sync(acc[i][j], af[i], bh[j], acc[i][j]);
                    if (NPASS == 2)
                        wmma::mma_sync(acc[i][j], af[i], bl[j], acc[i][j]);
                }
        }

        if (kt + 2 < NKT) load_stage((kt + 2) % XST, (kt + 2) * XBK);
        asm volatile("cp.async.commit_group;" ::: "memory");
    }

    // ---- fused epilogue: stage to smem, scatter to zxp packed layout + bias ----
    asm volatile("cp.async.wait_group 0;" ::: "memory");
    __syncthreads();                       // everyone done with pipeline smem
#pragma unroll
    for (int i = 0; i < 4; ++i)
#pragma unroll
        for (int j = 0; j < 2; ++j)
            wmma::store_matrix_sync(&S->stage[wm + 16 * i][wn + 16 * j], acc[i][j],
                                    XBN + 8, wmma::mem_row_major);
    __syncthreads();

    {
        const int j8 = tid & 7;
        const int cl = (tid >> 3) & 15;
        const int r0 = tid >> 7;           // 0..1
        const int g  = bn >> 10;
        const int c0 = (bn & 1023) >> 3;
        const float bval = bias[g * HH + (c0 + cl) * 8 + j8];
#pragma unroll 4
        for (int rr = r0; rr < XBM; rr += 2) {
            int m = bm + rr, t = m >> 6, row = m & 63;
            size_t o = (((size_t)t * PKCTA + c0 + cl) * BB + row) * 32 + g * 8 + j8;
            zxp[o] = S->stage[rr][cl * 8 + j8] + bval;
        }
    }
}

// ---------------- persistent recurrent kernel (fp16 2-pass, unchanged) --------
#define CH 64
#define NCH 16
#define HSTW 40
#define WST 32
#define ZST 36

struct PSmem {
    __half wh[HH][WST];
    __half wl[HH][WST];
    __half hws[8][3][16][HSTW];
    float zxs[BB][ZST];
    float zs[2][BB][ZST];
    float cs[BB][12];
};

__global__ __launch_bounds__(256) void lstm_persist_kernel(
    const float* __restrict__ zxp,
    const __half* __restrict__ wph,
    const __half* __restrict__ wpl,
    __half* __restrict__ hseq,
    float* __restrict__ hout_all,
    int* __restrict__ bar)
{
    extern __shared__ unsigned char smem_raw[];
    PSmem* S = (PSmem*)smem_raw;

    const int tid  = threadIdx.x;
    const int warp = tid >> 5;
    const int lane = tid & 31;
    const int cblk = blockIdx.x;
    const int mt   = warp & 3;
    const int kh   = warp >> 2;
    const int wrow = mt * 16;

    for (int i = tid; i < HH * 4; i += 256) {
        int row = i >> 2, off = (i & 3) * 8;
        cpa16(&S->wh[row][off], wph + ((size_t)cblk * HH + row) * 32 + off);
        cpa16(&S->wl[row][off], wpl + ((size_t)cblk * HH + row) * 32 + off);
    }
    asm volatile("cp.async.commit_group;\ncp.async.wait_group 0;" ::: "memory");
    for (int e = tid; e < BB * 12; e += 256) ((float*)S->cs)[e] = 0.0f;
    __syncthreads();

    const int frow = tid >> 2;
    const int fjp  = tid & 3;

    for (int t = 0; t < TT; ++t) {
        const __half* hin = hseq + (size_t)t * BB * HH;
        __half* hout = hseq + (size_t)(t + 1) * BB * HH + (size_t)cblk * (BB * 8);

        {
            const float* zsrc = zxp + ((size_t)t * PKCTA + cblk) * (BB * 32);
#pragma unroll
            for (int p = 0; p < 2; ++p) {
                int i = tid + p * 256;
                int r = i >> 3, seg = i & 7;
                cpa16((char*)&S->zxs[r][0] + seg * 16, zsrc + r * 32 + seg * 4);
            }
        }

        if (t > 0) {
            const int* f = bar + t - 1;
            if (lane == 0) {
                while (ldrelax(f) < PKCTA) __nanosleep(32);
            }
            __syncwarp();
            int v;
            asm volatile("ld.acquire.gpu.global.b32 %0, [%1];" : "=r"(v) : "l"(f) : "memory");
        }

        auto wload = [&](int slot, int ic) {
            int cbbase = ic * 8 + kh * 4;
            int cbl = lane >> 3;
#pragma unroll
            for (int p = 0; p < 2; ++p) {
                int rlo = (lane & 7) + p * 8;
                size_t src = (((size_t)(cbbase + cbl)) * BB + wrow + rlo) * 8;
                cpa16(&S->hws[warp][slot][rlo][cbl * 8], hin + src);
            }
        };

        wload(0, 0);
        asm volatile("cp.async.commit_group;" ::: "memory");
        wload(1, 1);
        asm volatile("cp.async.commit_group;" ::: "memory");
        wload(2, 2);
        asm volatile("cp.async.commit_group;" ::: "memory");

        wmma::fragment<wmma::accumulator, 16, 16, 16, float> acc[2][2];
#pragma unroll
        for (int nt = 0; nt < 2; ++nt)
#pragma unroll
            for (int p = 0; p < 2; ++p) wmma::fill_fragment(acc[nt][p], 0.0f);

        for (int ic = 0; ic < NCH; ++ic) {
            asm volatile("cp.async.wait_group 2;" ::: "memory");
            int sl = ic % 3;

#pragma unroll
            for (int kk = 0; kk < 2; ++kk) {
                wmma::fragment<wmma::matrix_a, 16, 16, 16, __half, wmma::row_major> af;
                wmma::load_matrix_sync(af, &S->hws[warp][sl][0][kk * 16], HSTW);
                int krow = ic * CH + kh * 32 + kk * 16;
#pragma unroll
                for (int nt = 0; nt < 2; ++nt) {
                    wmma::fragment<wmma::matrix_b, 16, 16, 16, __half, wmma::row_major> bh, bl;
                    wmma::load_matrix_sync(bh, &S->wh[krow][nt * 16], WST);
                    wmma::load_matrix_sync(bl, &S->wl[krow][nt * 16], WST);
                    wmma::mma_sync(acc[nt][0], af, bh, acc[nt][0]);
                    wmma::mma_sync(acc[nt][1], af, bl, acc[nt][1]);
                }
            }

            if (ic + 3 < NCH) wload((ic + 3) % 3, ic + 3);
            asm volatile("cp.async.commit_group;" ::: "memory");
        }
        asm volatile("cp.async.wait_group 0;" ::: "memory");

#pragma unroll
        for (int nt = 0; nt < 2; ++nt) {
#pragma unroll
            for (int e = 0; e < acc[nt][0].num_elements; ++e)
                acc[nt][0].x[e] += acc[nt][1].x[e];
            wmma::store_matrix_sync(&S->zs[kh][mt * 16][nt * 16], acc[nt][0], ZST,
                                    wmma::mem_row_major);
        }
        __syncthreads();

        {
            float nh2[2];
#pragma unroll
            for (int q = 0; q < 2; ++q) {
                int j = fjp + q * 4;
                float zi = S->zs[0][frow][j]      + S->zs[1][frow][j]      + S->zxs[frow][j];
                float zj = S->zs[0][frow][8 + j]  + S->zs[1][frow][8 + j]  + S->zxs[frow][8 + j];
                float zf = S->zs[0][frow][16 + j] + S->zs[1][frow][16 + j] + S->zxs[frow][16 + j];
                float zo = S->zs[0][frow][24 + j] + S->zs[1][frow][24 + j] + S->zxs[frow][24 + j];
                float cold = S->cs[frow][j];
                float nc = cold * fsig(zf + 1.0f) + fsig(zi) * ftanh(zj);
                float nh = ftanh(nc) * fsig(zo);
                S->cs[frow][j] = nc;
                nh2[q] = nh;
                hout[frow * 8 + j] = __float2half(nh);
            }
            __syncthreads();
            if (tid == 0)
                asm volatile("red.release.gpu.global.add.u32 [%0], 1;"
                             :: "l"(bar + t) : "memory");
            if (hout_all) {
                size_t ob = (size_t)t * BB * HH + (size_t)frow * HH + cblk * 8;
                hout_all[ob + fjp] = nh2[0];
                hout_all[ob + fjp + 4] = nh2[1];
            }
        }
    }
}

// ---------------- launch ------------------------------------------------------
extern "C" void kernel_launch(void* const* d_in, const int* in_sizes, int n_in,
                              void* d_out, int out_size)
{
    const float* x  = (const float*)d_in[0];
    const float* W0 = (const float*)d_in[1];
    const float* b0 = (const float*)d_in[2];
    const float* W1 = (const float*)d_in[3];
    const float* b1 = (const float*)d_in[4];
    float* out = (float*)d_out;

    float* zxp;
    __half *hseq, *xf, *wxh, *wxl, *wph, *wpl;
    int* bar;
    cudaGetSymbolAddress((void**)&zxp,  g_zxp);
    cudaGetSymbolAddress((void**)&hseq, g_hseq);
    cudaGetSymbolAddress((void**)&xf,   g_xf);
    cudaGetSymbolAddress((void**)&wxh,  g_wxh);
    cudaGetSymbolAddress((void**)&wxl,  g_wxl);
    cudaGetSymbolAddress((void**)&wph,  g_wph);
    cudaGetSymbolAddress((void**)&wpl,  g_wpl);
    cudaGetSymbolAddress((void**)&bar,  g_bar);

    const int psmem = (int)sizeof(PSmem);
    cudaFuncSetAttribute(lstm_persist_kernel,
                         cudaFuncAttributeMaxDynamicSharedMemorySize, psmem);
    const int gsmem = (int)sizeof(GSmem);
    cudaFuncSetAttribute(gemm_x_f16<2>,
                         cudaFuncAttributeMaxDynamicSharedMemorySize, gsmem);
    cudaFuncSetAttribute(gemm_x_f16<1>,
                         cudaFuncAttributeMaxDynamicSharedMemorySize, gsmem);

    const dim3 ggrid(NG / XBN, TBm / XBM);   // (32, 128)

    // ---- layer 0 (2-pass W: errors here amplify through both layers) ----
    tof16_kernel<<<2048, 256>>>(x, xf, (size_t)TBm * HH);
    prep_wx_kernel<<<2048, 256>>>(W0, wxh, wxl);
    prep_w_kernel<<<2048, 256>>>(W0, wph, wpl);
    init_state_kernel<<<(BB * HH + 255) / 256, 256>>>(hseq, bar);
    gemm_x_f16<2><<<ggrid, 256, gsmem>>>(xf, hseq, wxh, wxl, b0, zxp, 0);
    lstm_persist_kernel<<<PKCTA, 256, psmem>>>(zxp, wph, wpl, hseq, (float*)0, bar);

    // ---- layer 1 (1-pass W: error amplifies through one layer only) ----
    prep_wx_kernel<<<2048, 256>>>(W1, wxh, wxl);
    prep_w_kernel<<<2048, 256>>>(W1, wph, wpl);
    gemm_x_f16<1><<<ggrid, 256, gsmem>>>(xf, hseq, wxh, wxl, b1, zxp, 1);
    init_state_kernel<<<(BB * HH + 255) / 256, 256>>>(hseq, bar + TT);
    lstm_persist_kernel<<<PKCTA, 256, psmem>>>(zxp, wph, wpl, hseq, out, bar + TT);
}

// round 16
// speedup vs baseline: 1.8700x; 1.1219x over previous
#include <cuda_runtime.h>
#include <cuda_bf16.h>
#include <cuda_fp16.h>
#include <mma.h>
#include <math.h>

using namespace nvcuda;

// Problem shape (fixed): T=256, B=64, D=H=1024
#define TT 256
#define BB 64
#define HH 1024
#define NG 4096      // 4*H
#define TBm 16384    // T*B
#define PKCTA 128    // persistent CTAs

// ---------------- scratch (device globals) ------------------------------------
__device__ float g_zxp[(size_t)TBm * NG];      // packed x-projection (+bias)
// h sequence, CTA-block-major: [slot(257)][cb(128)][row(64)][8] fp16
__device__ __align__(128) __half g_hseq[(size_t)(TT + 1) * BB * HH];
__device__ __align__(128) __half g_xf[(size_t)TBm * HH];     // x fp16 (row-major)
__device__ __align__(128) __half g_wxh[(size_t)HH * NG];     // input-W fp16 hi
__device__ __align__(128) __half g_wxl[(size_t)HH * NG];     // input-W fp16 lo
__device__ __align__(128) __half g_wph[(size_t)HH * NG];     // packed recurrent W hi
__device__ __align__(128) __half g_wpl[(size_t)HH * NG];     // packed recurrent W lo
__device__ __align__(16) int g_bar[2 * TT];

// ---------------- helpers ------------------------------------------------------
__device__ __forceinline__ void split_f16(float x, __half& hi, __half& lo) {
    hi = __float2half(x);
    lo = __float2half(x - __half2float(hi));
}
__device__ __forceinline__ float fsig(float x) { return __fdividef(1.0f, 1.0f + __expf(-x)); }
__device__ __forceinline__ float ftanh(float x) { return 1.0f - __fdividef(2.0f, __expf(2.0f * x) + 1.0f); }
__device__ __forceinline__ void cpa16(void* dst, const void* src) {
    unsigned d = (unsigned)__cvta_generic_to_shared(dst);
    asm volatile("cp.async.cg.shared.global [%0], [%1], 16;" :: "r"(d), "l"(src));
}
__device__ __forceinline__ int ldrelax(const int* p) {
    int v; asm volatile("ld.relaxed.gpu.global.b32 %0, [%1];" : "=r"(v) : "l"(p)); return v;
}

__global__ void init_state_kernel(__half* hseq, int* bar) {
    int i = blockIdx.x * blockDim.x + threadIdx.x;
    if (i < BB * HH) hseq[i] = __float2half(0.0f);   // slot 0 = h(0) = 0
    if (i < TT) bar[i] = 0;
}

// fp32 -> single fp16 plane
__global__ void tof16_kernel(const float* __restrict__ a, __half* __restrict__ o, size_t n) {
    for (size_t i = (size_t)blockIdx.x * blockDim.x + threadIdx.x; i < n;
         i += (size_t)gridDim.x * blockDim.x)
        o[i] = __float2half(a[i]);
}

// Fused W prep: ONE pass over W[2048][4096].
// rows 0..1023  -> input-W fp16 planes (hi always, lo iff NEED_XLO)
// rows 1024..2047 -> packed recurrent slices (hi always, lo iff NEED_RLO)
template <int NEED_XLO, int NEED_RLO>
__global__ void prep_w_all(const float* __restrict__ W,
                           __half* __restrict__ xh, __half* __restrict__ xl,
                           __half* __restrict__ rh, __half* __restrict__ rl) {
    for (size_t o = (size_t)blockIdx.x * blockDim.x + threadIdx.x;
         o < (size_t)2 * HH * NG; o += (size_t)gridDim.x * blockDim.x) {
        int col = (int)(o & 4095);
        int row = (int)(o >> 12);
        float v = W[o];
        __half h, l; split_f16(v, h, l);
        if (row < HH) {
            size_t oo = (size_t)row * NG + col;
            xh[oo] = h;
            if (NEED_XLO) xl[oo] = l;
        } else {
            int k = row - HH;
            int g = col >> 10, rem = col & 1023;
            int c = rem >> 3, j = rem & 7;
            size_t oo = ((size_t)c * HH + k) * 32 + g * 8 + j;
            rh[oo] = h;
            if (NEED_RLO) rl[oo] = l;
        }
    }
}

// ---------------- big input-projection GEMM (fp16, fused bias+repack) ---------
#define XBM 128
#define XBN 128
#define XBK 32
#define XST 3

struct GSmem {
    union {
        struct {
            __half Af[XST][XBM][XBK + 8];
            __half Bh[XST][XBK][XBN + 8];
            __half Bl[XST][XBK][XBN + 8];
        } p;
        float stage[XBM][XBN + 8];
    };
};

template <int NPASS>
__global__ __launch_bounds__(256) void gemm_x_f16(
    const __half* __restrict__ Af, const __half* __restrict__ hseq,
    const __half* __restrict__ Bph, const __half* __restrict__ Bpl,
    const float* __restrict__ bias, float* __restrict__ zxp, int seq)
{
    extern __shared__ unsigned char sraw[];
    GSmem* S = (GSmem*)sraw;

    const int bm = blockIdx.y * XBM;
    const int bn = blockIdx.x * XBN;
    const int tid = threadIdx.x;
    const int warp = tid >> 5;
    const int wm = (warp >> 2) * 64;
    const int wn = (warp & 3) * 32;

    auto load_stage = [&](int s, int kb) {
#pragma unroll
        for (int p = 0; p < 2; ++p) {
            int i = tid + p * 256;
            int r = i >> 2, cbl = i & 3;
            if (seq == 0) {
                cpa16(&S->p.Af[s][r][cbl * 8], Af + (size_t)(bm + r) * HH + kb + cbl * 8);
            } else {
                int m = bm + r, t0 = m >> 6, row = m & 63;
                size_t src = (((size_t)(t0 + 1) * PKCTA + (kb >> 3) + cbl) * BB + row) * 8;
                cpa16(&S->p.Af[s][r][cbl * 8], hseq + src);
            }
        }
#pragma unroll
        for (int p = 0; p < 2; ++p) {
            int i = tid + p * 256;
            int r = i >> 4, off = (i & 15) * 8;
            cpa16(&S->p.Bh[s][r][off], Bph + (size_t)(kb + r) * NG + bn + off);
            if (NPASS == 2)
                cpa16(&S->p.Bl[s][r][off], Bpl + (size_t)(kb + r) * NG + bn + off);
        }
    };

    load_stage(0, 0);
    asm volatile("cp.async.commit_group;" ::: "memory");
    load_stage(1, XBK);
    asm volatile("cp.async.commit_group;" ::: "memory");

    wmma::fragment<wmma::accumulator, 16, 16, 16, float> acc[4][2];
#pragma unroll
    for (int i = 0; i < 4; ++i)
#pragma unroll
        for (int j = 0; j < 2; ++j) wmma::fill_fragment(acc[i][j], 0.0f);

    const int NKT = HH / XBK;   // 32
    for (int kt = 0; kt < NKT; ++kt) {
        asm volatile("cp.async.wait_group 1;" ::: "memory");
        __syncthreads();
        int s = kt % XST;

#pragma unroll
        for (int kk = 0; kk < XBK; kk += 16) {
            wmma::fragment<wmma::matrix_a, 16, 16, 16, __half, wmma::row_major> af[4];
            wmma::fragment<wmma::matrix_b, 16, 16, 16, __half, wmma::row_major> bh[2], bl[2];
#pragma unroll
            for (int i = 0; i < 4; ++i)
                wmma::load_matrix_sync(af[i], &S->p.Af[s][wm + 16 * i][kk], XBK + 8);
#pragma unroll
            for (int j = 0; j < 2; ++j) {
                wmma::load_matrix_sync(bh[j], &S->p.Bh[s][kk][wn + 16 * j], XBN + 8);
                if (NPASS == 2)
                    wmma::load_matrix_sync(bl[j], &S->p.Bl[s][kk][wn + 16 * j], XBN + 8);
            }
#pragma unroll
            for (int i = 0; i < 4; ++i)
#pragma unroll
                for (int j = 0; j < 2; ++j) {
                    wmma::mma_sync(acc[i][j], af[i], bh[j], acc[i][j]);
                    if (NPASS == 2)
                        wmma::mma_sync(acc[i][j], af[i], bl[j], acc[i][j]);
                }
        }

        if (kt + 2 < NKT) load_stage((kt + 2) % XST, (kt + 2) * XBK);
        asm volatile("cp.async.commit_group;" ::: "memory");
    }

    // fused epilogue: stage to smem, scatter to zxp packed layout + bias
    asm volatile("cp.async.wait_group 0;" ::: "memory");
    __syncthreads();
#pragma unroll
    for (int i = 0; i < 4; ++i)
#pragma unroll
        for (int j = 0; j < 2; ++j)
            wmma::store_matrix_sync(&S->stage[wm + 16 * i][wn + 16 * j], acc[i][j],
                                    XBN + 8, wmma::mem_row_major);
    __syncthreads();

    {
        const int j8 = tid & 7;
        const int cl = (tid >> 3) & 15;
        const int r0 = tid >> 7;
        const int g  = bn >> 10;
        const int c0 = (bn & 1023) >> 3;
        const float bval = bias[g * HH + (c0 + cl) * 8 + j8];
#pragma unroll 4
        for (int rr = r0; rr < XBM; rr += 2) {
            int m = bm + rr, t = m >> 6, row = m & 63;
            size_t o = (((size_t)t * PKCTA + c0 + cl) * BB + row) * 32 + g * 8 + j8;
            zxp[o] = S->stage[rr][cl * 8 + j8] + bval;
        }
    }
}

// ---------------- persistent recurrent kernel (fp16, NPASS template) ----------
#define CH 64
#define NCH 16
#define HSTW 40
#define WST 32
#define ZST 36

struct PSmem {
    __half wh[HH][WST];
    __half wl[HH][WST];
    __half hws[8][3][16][HSTW];
    float zxs[BB][ZST];
    float zs[2][BB][ZST];
    float cs[BB][12];
};

template <int NPASS>
__global__ __launch_bounds__(256) void lstm_persist_kernel(
    const float* __restrict__ zxp,
    const __half* __restrict__ wph,
    const __half* __restrict__ wpl,
    __half* __restrict__ hseq,
    float* __restrict__ hout_all,
    int* __restrict__ bar)
{
    extern __shared__ unsigned char smem_raw[];
    PSmem* S = (PSmem*)smem_raw;

    const int tid  = threadIdx.x;
    const int warp = tid >> 5;
    const int lane = tid & 31;
    const int cblk = blockIdx.x;
    const int mt   = warp & 3;
    const int kh   = warp >> 2;
    const int wrow = mt * 16;

    for (int i = tid; i < HH * 4; i += 256) {
        int row = i >> 2, off = (i & 3) * 8;
        cpa16(&S->wh[row][off], wph + ((size_t)cblk * HH + row) * 32 + off);
        if (NPASS == 2)
            cpa16(&S->wl[row][off], wpl + ((size_t)cblk * HH + row) * 32 + off);
    }
    asm volatile("cp.async.commit_group;\ncp.async.wait_group 0;" ::: "memory");
    for (int e = tid; e < BB * 12; e += 256) ((float*)S->cs)[e] = 0.0f;
    __syncthreads();

    const int frow = tid >> 2;
    const int fjp  = tid & 3;

    for (int t = 0; t < TT; ++t) {
        const __half* hin = hseq + (size_t)t * BB * HH;
        __half* hout = hseq + (size_t)(t + 1) * BB * HH + (size_t)cblk * (BB * 8);

        {
            const float* zsrc = zxp + ((size_t)t * PKCTA + cblk) * (BB * 32);
#pragma unroll
            for (int p = 0; p < 2; ++p) {
                int i = tid + p * 256;
                int r = i >> 3, seg = i & 7;
                cpa16((char*)&S->zxs[r][0] + seg * 16, zsrc + r * 32 + seg * 4);
            }
        }

        if (t > 0) {
            const int* f = bar + t - 1;
            if (lane == 0) {
                while (ldrelax(f) < PKCTA) __nanosleep(32);
            }
            __syncwarp();
            int v;
            asm volatile("ld.acquire.gpu.global.b32 %0, [%1];" : "=r"(v) : "l"(f) : "memory");
        }

        auto wload = [&](int slot, int ic) {
            int cbbase = ic * 8 + kh * 4;
            int cbl = lane >> 3;
#pragma unroll
            for (int p = 0; p < 2; ++p) {
                int rlo = (lane & 7) + p * 8;
                size_t src = (((size_t)(cbbase + cbl)) * BB + wrow + rlo) * 8;
                cpa16(&S->hws[warp][slot][rlo][cbl * 8], hin + src);
            }
        };

        wload(0, 0);
        asm volatile("cp.async.commit_group;" ::: "memory");
        wload(1, 1);
        asm volatile("cp.async.commit_group;" ::: "memory");
        wload(2, 2);
        asm volatile("cp.async.commit_group;" ::: "memory");

        wmma::fragment<wmma::accumulator, 16, 16, 16, float> acc[2][2];
#pragma unroll
        for (int nt = 0; nt < 2; ++nt)
#pragma unroll
            for (int p = 0; p < NPASS; ++p) wmma::fill_fragment(acc[nt][p], 0.0f);

        for (int ic = 0; ic < NCH; ++ic) {
            asm volatile("cp.async.wait_group 2;" ::: "memory");
            int sl = ic % 3;

#pragma unroll
            for (int kk = 0; kk < 2; ++kk) {
                wmma::fragment<wmma::matrix_a, 16, 16, 16, __half, wmma::row_major> af;
                wmma::load_matrix_sync(af, &S->hws[warp][sl][0][kk * 16], HSTW);
                int krow = ic * CH + kh * 32 + kk * 16;
#pragma unroll
                for (int nt = 0; nt < 2; ++nt) {
                    wmma::fragment<wmma::matrix_b, 16, 16, 16, __half, wmma::row_major> bh, bl;
                    wmma::load_matrix_sync(bh, &S->wh[krow][nt * 16], WST);
                    if (NPASS == 2)
                        wmma::load_matrix_sync(bl, &S->wl[krow][nt * 16], WST);
                    wmma::mma_sync(acc[nt][0], af, bh, acc[nt][0]);
                    if (NPASS == 2)
                        wmma::mma_sync(acc[nt][1], af, bl, acc[nt][1]);
                }
            }

            if (ic + 3 < NCH) wload((ic + 3) % 3, ic + 3);
            asm volatile("cp.async.commit_group;" ::: "memory");
        }
        asm volatile("cp.async.wait_group 0;" ::: "memory");

#pragma unroll
        for (int nt = 0; nt < 2; ++nt) {
            if (NPASS == 2) {
#pragma unroll
                for (int e = 0; e < acc[nt][0].num_elements; ++e)
                    acc[nt][0].x[e] += acc[nt][1].x[e];
            }
            wmma::store_matrix_sync(&S->zs[kh][mt * 16][nt * 16], acc[nt][0], ZST,
                                    wmma::mem_row_major);
        }
        __syncthreads();

        {
            float nh2[2];
#pragma unroll
            for (int q = 0; q < 2; ++q) {
                int j = fjp + q * 4;
                float zi = S->zs[0][frow][j]      + S->zs[1][frow][j]      + S->zxs[frow][j];
                float zj = S->zs[0][frow][8 + j]  + S->zs[1][frow][8 + j]  + S->zxs[frow][8 + j];
                float zf = S->zs[0][frow][16 + j] + S->zs[1][frow][16 + j] + S->zxs[frow][16 + j];
                float zo = S->zs[0][frow][24 + j] + S->zs[1][frow][24 + j] + S->zxs[frow][24 + j];
                float cold = S->cs[frow][j];
                float nc = cold * fsig(zf + 1.0f) + fsig(zi) * ftanh(zj);
                float nh = ftanh(nc) * fsig(zo);
                S->cs[frow][j] = nc;
                nh2[q] = nh;
                hout[frow * 8 + j] = __float2half(nh);
            }
            __syncthreads();
            if (tid == 0)
                asm volatile("red.release.gpu.global.add.u32 [%0], 1;"
                             :: "l"(bar + t) : "memory");
            if (hout_all) {
                size_t ob = (size_t)t * BB * HH + (size_t)frow * HH + cblk * 8;
                hout_all[ob + fjp] = nh2[0];
                hout_all[ob + fjp + 4] = nh2[1];
            }
        }
    }
}

// ---------------- launch ------------------------------------------------------
extern "C" void kernel_launch(void* const* d_in, const int* in_sizes, int n_in,
                              void* d_out, int out_size)
{
    const float* x  = (const float*)d_in[0];
    const float* W0 = (const float*)d_in[1];
    const float* b0 = (const float*)d_in[2];
    const float* W1 = (const float*)d_in[3];
    const float* b1 = (const float*)d_in[4];
    float* out = (float*)d_out;

    float* zxp;
    __half *hseq, *xf, *wxh, *wxl, *wph, *wpl;
    int* bar;
    cudaGetSymbolAddress((void**)&zxp,  g_zxp);
    cudaGetSymbolAddress((void**)&hseq, g_hseq);
    cudaGetSymbolAddress((void**)&xf,   g_xf);
    cudaGetSymbolAddress((void**)&wxh,  g_wxh);
    cudaGetSymbolAddress((void**)&wxl,  g_wxl);
    cudaGetSymbolAddress((void**)&wph,  g_wph);
    cudaGetSymbolAddress((void**)&wpl,  g_wpl);
    cudaGetSymbolAddress((void**)&bar,  g_bar);

    const int psmem = (int)sizeof(PSmem);
    cudaFuncSetAttribute(lstm_persist_kernel<2>,
                         cudaFuncAttributeMaxDynamicSharedMemorySize, psmem);
    cudaFuncSetAttribute(lstm_persist_kernel<1>,
                         cudaFuncAttributeMaxDynamicSharedMemorySize, psmem);
    const int gsmem = (int)sizeof(GSmem);
    cudaFuncSetAttribute(gemm_x_f16<2>,
                         cudaFuncAttributeMaxDynamicSharedMemorySize, gsmem);
    cudaFuncSetAttribute(gemm_x_f16<1>,
                         cudaFuncAttributeMaxDynamicSharedMemorySize, gsmem);

    const dim3 ggrid(NG / XBN, TBm / XBM);   // (32, 128)

    // ---- layer 0 (2-pass everywhere: errors amplify through both layers) ----
    tof16_kernel<<<2048, 256>>>(x, xf, (size_t)TBm * HH);
    prep_w_all<1, 1><<<4096, 256>>>(W0, wxh, wxl, wph, wpl);
    init_state_kernel<<<(BB * HH + 255) / 256, 256>>>(hseq, bar);
    gemm_x_f16<2><<<ggrid, 256, gsmem>>>(xf, hseq, wxh, wxl, b0, zxp, 0);
    lstm_persist_kernel<2><<<PKCTA, 256, psmem>>>(zxp, wph, wpl, hseq, (float*)0, bar);

    // ---- layer 1 (1-pass gemm AND 1-pass recurrent: single-layer amplification) ----
    prep_w_all<0, 0><<<4096, 256>>>(W1, wxh, wxl, wph, wpl);
    gemm_x_f16<1><<<ggrid, 256, gsmem>>>(xf, hseq, wxh, wxl, b1, zxp, 1);
    init_state_kernel<<<(BB * HH + 255) / 256, 256>>>(hseq, bar + TT);
    lstm_persist_kernel<1><<<PKCTA, 256, psmem>>>(zxp, wph, wpl, hseq, out, bar + TT);
}